// round 1
// baseline (speedup 1.0000x reference)
#include <cuda_runtime.h>
#include <cstdint>

// Problem constants
#define BB   4
#define WW   256
#define CSEQ 32
#define CDIM 1024
#define NH   16
#define HD   64
#define BW   (BB*WW)          // 1024
#define MROWS (BW*CSEQ)       // 32768

// Scratch (device globals: allocation-free rule)
__device__ float g_KV[(size_t)MROWS * 2048]; // per row: [0..1023]=K, [1024..2047]=V
__device__ float g_q [(size_t)BW * CDIM];    // gathered query rows
__device__ float g_o [(size_t)BW * CDIM];    // attention output (gathered row)
__device__ int   g_last[BW];

// ---------------------------------------------------------------------------
// lengths - 1
__global__ void k_last(const int* __restrict__ mask) {
    int i = blockIdx.x * blockDim.x + threadIdx.x;
    if (i < BW) {
        int s = 0;
        #pragma unroll
        for (int j = 0; j < CSEQ; j++) s += mask[i * CSEQ + j];
        g_last[i] = s - 1;
    }
}

// ---------------------------------------------------------------------------
// Classic fp32 tiled GEMM: C[M,N] = A'[M,K] * B[K,N]
// MODE 0: A row m at A + m*lda
// MODE 1: A row m at A + (m*CSEQ + g_last[m])*lda          (gather query row)
// MODE 2: A row m at A + m*lda, plus pos[(m%WW)*CDIM + k]  (add pos_emb)
// BM=BN=128, BK=8, 256 threads, 8x8 per thread. All dims multiples of tiles.
template <int MODE>
__global__ __launch_bounds__(256)
void sgemm(const float* __restrict__ A, const float* __restrict__ B,
           float* __restrict__ Cc, int K, int lda, int ldb, int ldc,
           const float* __restrict__ pos) {
    __shared__ float As[8][128];
    __shared__ float Bs[8][128];

    const int tid  = threadIdx.x;
    const int row0 = blockIdx.y * 128;
    const int col0 = blockIdx.x * 128;

    const int a_r = tid >> 1;            // 0..127
    const int a_k = (tid & 1) * 4;       // 0 / 4
    const int b_r = tid >> 5;            // 0..7
    const int b_c = (tid & 31) * 4;      // 0..124

    const int ty = tid >> 4;             // 0..15
    const int tx = tid & 15;             // 0..15

    float acc[8][8];
    #pragma unroll
    for (int i = 0; i < 8; i++)
        #pragma unroll
        for (int j = 0; j < 8; j++) acc[i][j] = 0.f;

    const int grow = row0 + a_r;
    const float* arow;
    if (MODE == 1) arow = A + ((size_t)grow * CSEQ + g_last[grow]) * (size_t)lda;
    else           arow = A + (size_t)grow * (size_t)lda;
    const float* prow = (MODE == 2) ? (pos + (size_t)(grow & (WW - 1)) * CDIM) : nullptr;

    for (int k0 = 0; k0 < K; k0 += 8) {
        float4 av = *(const float4*)(arow + k0 + a_k);
        if (MODE == 2) {
            const float* pr = prow + k0 + a_k;
            av.x += pr[0]; av.y += pr[1]; av.z += pr[2]; av.w += pr[3];
        }
        As[a_k + 0][a_r] = av.x;
        As[a_k + 1][a_r] = av.y;
        As[a_k + 2][a_r] = av.z;
        As[a_k + 3][a_r] = av.w;

        float4 bv = *(const float4*)(B + (size_t)(k0 + b_r) * (size_t)ldb + col0 + b_c);
        *(float4*)&Bs[b_r][b_c] = bv;

        __syncthreads();

        #pragma unroll
        for (int kk = 0; kk < 8; kk++) {
            float a[8], b[8];
            #pragma unroll
            for (int i = 0; i < 8; i++) a[i] = As[kk][ty * 8 + i];
            #pragma unroll
            for (int j = 0; j < 8; j++) b[j] = Bs[kk][tx * 8 + j];
            #pragma unroll
            for (int i = 0; i < 8; i++)
                #pragma unroll
                for (int j = 0; j < 8; j++)
                    acc[i][j] = fmaf(a[i], b[j], acc[i][j]);
        }
        __syncthreads();
    }

    #pragma unroll
    for (int i = 0; i < 8; i++) {
        int r = row0 + ty * 8 + i;
        float4* cp = (float4*)(Cc + (size_t)r * (size_t)ldc + col0 + tx * 8);
        cp[0] = make_float4(acc[i][0], acc[i][1], acc[i][2], acc[i][3]);
        cp[1] = make_float4(acc[i][4], acc[i][5], acc[i][6], acc[i][7]);
    }
}

// ---------------------------------------------------------------------------
// Single-query causal attention per (b,w,h). Block = 64 threads.
__global__ __launch_bounds__(64)
void k_attn() {
    const int bwh = blockIdx.x;
    const int bw  = bwh >> 4;
    const int h   = bwh & 15;
    const int L   = g_last[bw] + 1;

    const float* Kp = g_KV + (size_t)bw * CSEQ * 2048 + h * HD;
    const float* Vp = Kp + 1024;
    const float* qp = g_q  + (size_t)bw * CDIM + h * HD;

    __shared__ float q[HD];
    __shared__ float p[CSEQ];

    const int t = threadIdx.x;
    q[t] = qp[t];
    __syncthreads();

    if (t < 32) {
        float s = -INFINITY;
        if (t < L) {
            const float* kr = Kp + (size_t)t * 2048;
            float a = 0.f;
            #pragma unroll
            for (int d = 0; d < HD; d++) a = fmaf(q[d], kr[d], a);
            s = a * 0.125f;  // 1/sqrt(64)
        }
        float m = s;
        #pragma unroll
        for (int off = 16; off; off >>= 1)
            m = fmaxf(m, __shfl_xor_sync(0xffffffffu, m, off));
        float e = (t < L) ? __expf(s - m) : 0.f;
        float sum = e;
        #pragma unroll
        for (int off = 16; off; off >>= 1)
            sum += __shfl_xor_sync(0xffffffffu, sum, off);
        p[t] = e / sum;
    }
    __syncthreads();

    float acc = 0.f;
    for (int j = 0; j < L; j++)
        acc = fmaf(p[j], Vp[(size_t)j * 2048 + t], acc);
    g_o[(size_t)bw * CDIM + h * HD + t] = acc;
}

// ---------------------------------------------------------------------------
extern "C" void kernel_launch(void* const* d_in, const int* in_sizes, int n_in,
                              void* d_out, int out_size) {
    const float* x      = (const float*)d_in[0];  // (4,256,32,1024)
    const int*   mask   = (const int*)  d_in[1];  // (4,256,32)
    const float* pos    = (const float*)d_in[2];  // (256,1024)
    const float* attn_w = (const float*)d_in[3];  // (1024,3072)
    const float* proj_w = (const float*)d_in[4];  // (1024,1024)
    float*       out    = (float*)d_out;          // (4,256,1024)

    float* kv; cudaGetSymbolAddress((void**)&kv, g_KV);
    float* qb; cudaGetSymbolAddress((void**)&qb, g_q);
    float* ob; cudaGetSymbolAddress((void**)&ob, g_o);

    // 1) last index per (b,w)
    k_last<<<4, 256>>>(mask);

    // 2) Q for gathered rows only: [1024,1024] = gather(x) @ attn_w[:, :1024]
    {
        dim3 grid(CDIM / 128, BW / 128);  // (8, 8)
        sgemm<1><<<grid, 256>>>(x, attn_w, qb, CDIM, CDIM, 3 * CDIM, CDIM, nullptr);
    }

    // 3) K,V: [32768,2048] = x @ attn_w[:, 1024:3072]   (dominant GEMM)
    {
        dim3 grid(2048 / 128, MROWS / 128); // (16, 256)
        sgemm<0><<<grid, 256>>>(x, attn_w + CDIM, kv, CDIM, CDIM, 3 * CDIM, 2048, nullptr);
    }

    // 4) single-row causal attention per (b,w,h)
    k_attn<<<BW * NH, 64>>>();

    // 5) out = (o_last + pos_emb) @ proj_w
    {
        dim3 grid(CDIM / 128, BW / 128);  // (8, 8)
        sgemm<2><<<grid, 256>>>(ob, proj_w, out, CDIM, CDIM, CDIM, CDIM, pos);
    }
}

// round 2
// speedup vs baseline: 4.2805x; 4.2805x over previous
#include <cuda_runtime.h>
#include <cstdint>
#include <math.h>

// Problem constants
#define BB   4
#define WW   256
#define CSEQ 32
#define CDIM 1024
#define NH   16
#define HD   64
#define BW   (BB*WW)          // 1024

// Scratch (device globals: allocation-free rule)
__device__ float g_q [(size_t)BW * CDIM];        // gathered query rows      [bw][C]
__device__ float g_t [(size_t)BW * NH * CDIM];   // t = Wk_h @ q_h           [bw][h][C]
__device__ float g_A [(size_t)BW * NH * CDIM];   // mixed rows p_h @ X       [bw][h][C]
__device__ float g_o [(size_t)BW * CDIM];        // attention output         [bw][C]
__device__ int   g_last[BW];

// ---------------------------------------------------------------------------
// lengths - 1
__global__ void k_last(const int* __restrict__ mask) {
    int i = blockIdx.x * blockDim.x + threadIdx.x;
    if (i < BW) {
        int s = 0;
        #pragma unroll
        for (int j = 0; j < CSEQ; j++) s += mask[i * CSEQ + j];
        g_last[i] = s - 1;
    }
}

// ---------------------------------------------------------------------------
// Classic fp32 tiled GEMM: C[M,N] = A'[M,K] * B[K,N]
// MODE 1: A row m at A + (m*CSEQ + g_last[m])*lda          (gather query row)
// MODE 2: A row m at A + m*lda, plus pos[(m%WW)*CDIM + k]  (add pos_emb)
template <int MODE>
__global__ __launch_bounds__(256)
void sgemm(const float* __restrict__ A, const float* __restrict__ B,
           float* __restrict__ Cc, int K, int lda, int ldb, int ldc,
           const float* __restrict__ pos) {
    __shared__ float As[8][128];
    __shared__ float Bs[8][128];

    const int tid  = threadIdx.x;
    const int row0 = blockIdx.y * 128;
    const int col0 = blockIdx.x * 128;

    const int a_r = tid >> 1;
    const int a_k = (tid & 1) * 4;
    const int b_r = tid >> 5;
    const int b_c = (tid & 31) * 4;

    const int ty = tid >> 4;
    const int tx = tid & 15;

    float acc[8][8];
    #pragma unroll
    for (int i = 0; i < 8; i++)
        #pragma unroll
        for (int j = 0; j < 8; j++) acc[i][j] = 0.f;

    const int grow = row0 + a_r;
    const float* arow;
    if (MODE == 1) arow = A + ((size_t)grow * CSEQ + g_last[grow]) * (size_t)lda;
    else           arow = A + (size_t)grow * (size_t)lda;
    const float* prow = (MODE == 2) ? (pos + (size_t)(grow & (WW - 1)) * CDIM) : nullptr;

    for (int k0 = 0; k0 < K; k0 += 8) {
        float4 av = *(const float4*)(arow + k0 + a_k);
        if (MODE == 2) {
            const float* pr = prow + k0 + a_k;
            av.x += pr[0]; av.y += pr[1]; av.z += pr[2]; av.w += pr[3];
        }
        As[a_k + 0][a_r] = av.x;
        As[a_k + 1][a_r] = av.y;
        As[a_k + 2][a_r] = av.z;
        As[a_k + 3][a_r] = av.w;

        *(float4*)&Bs[b_r][b_c] =
            *(const float4*)(B + (size_t)(k0 + b_r) * (size_t)ldb + col0 + b_c);

        __syncthreads();

        #pragma unroll
        for (int kk = 0; kk < 8; kk++) {
            float a[8], b[8];
            #pragma unroll
            for (int i = 0; i < 8; i++) a[i] = As[kk][ty * 8 + i];
            #pragma unroll
            for (int j = 0; j < 8; j++) b[j] = Bs[kk][tx * 8 + j];
            #pragma unroll
            for (int i = 0; i < 8; i++)
                #pragma unroll
                for (int j = 0; j < 8; j++)
                    acc[i][j] = fmaf(a[i], b[j], acc[i][j]);
        }
        __syncthreads();
    }

    #pragma unroll
    for (int i = 0; i < 8; i++) {
        int r = row0 + ty * 8 + i;
        float4* cp = (float4*)(Cc + (size_t)r * (size_t)ldc + col0 + tx * 8);
        cp[0] = make_float4(acc[i][0], acc[i][1], acc[i][2], acc[i][3]);
        cp[1] = make_float4(acc[i][4], acc[i][5], acc[i][6], acc[i][7]);
    }
}

// ---------------------------------------------------------------------------
// t[bw][h][c] = sum_d q[bw, h*64+d] * Wk[c, h*64+d],  Wk[c,hd] = attn_w[c*3072 + 1024 + h*64 + d]
// Per head: GEMM M=1024(bw) x N=1024(c) x K=64.  grid (8 cblk, 8 bwblk, 16 h)
__global__ __launch_bounds__(256)
void k_tgemm(const float* __restrict__ attn_w) {
    __shared__ float As[16][128];
    __shared__ float Bs[16][128];

    const int h    = blockIdx.z;
    const int col0 = blockIdx.x * 128;
    const int row0 = blockIdx.y * 128;
    const int tid  = threadIdx.x;
    const int ty = tid >> 4, tx = tid & 15;

    float acc[8][8];
    #pragma unroll
    for (int i = 0; i < 8; i++)
        #pragma unroll
        for (int j = 0; j < 8; j++) acc[i][j] = 0.f;

    const float* qbase = g_q + (size_t)row0 * CDIM + h * HD;
    const float* wbase = attn_w + (size_t)col0 * 3072 + CDIM + h * HD;

    for (int k0 = 0; k0 < HD; k0 += 16) {
        // A: q tile [128 bw x 16 k]
        {
            int m = tid >> 1, kq = (tid & 1) * 8;
            float4 v0 = *(const float4*)(qbase + (size_t)m * CDIM + k0 + kq);
            float4 v1 = *(const float4*)(qbase + (size_t)m * CDIM + k0 + kq + 4);
            As[kq + 0][m] = v0.x; As[kq + 1][m] = v0.y; As[kq + 2][m] = v0.z; As[kq + 3][m] = v0.w;
            As[kq + 4][m] = v1.x; As[kq + 5][m] = v1.y; As[kq + 6][m] = v1.z; As[kq + 7][m] = v1.w;
        }
        // B: Wk^T tile -> Bs[k][n] = attn_w[(col0+n)*3072 + 1024 + h*64 + k0+k]
        {
            int n = tid >> 1, kq = (tid & 1) * 8;
            float4 v0 = *(const float4*)(wbase + (size_t)n * 3072 + k0 + kq);
            float4 v1 = *(const float4*)(wbase + (size_t)n * 3072 + k0 + kq + 4);
            Bs[kq + 0][n] = v0.x; Bs[kq + 1][n] = v0.y; Bs[kq + 2][n] = v0.z; Bs[kq + 3][n] = v0.w;
            Bs[kq + 4][n] = v1.x; Bs[kq + 5][n] = v1.y; Bs[kq + 6][n] = v1.z; Bs[kq + 7][n] = v1.w;
        }
        __syncthreads();

        #pragma unroll
        for (int kk = 0; kk < 16; kk++) {
            float a[8], b[8];
            #pragma unroll
            for (int i = 0; i < 8; i++) a[i] = As[kk][ty * 8 + i];
            #pragma unroll
            for (int j = 0; j < 8; j++) b[j] = Bs[kk][tx * 8 + j];
            #pragma unroll
            for (int i = 0; i < 8; i++)
                #pragma unroll
                for (int j = 0; j < 8; j++)
                    acc[i][j] = fmaf(a[i], b[j], acc[i][j]);
        }
        __syncthreads();
    }

    #pragma unroll
    for (int i = 0; i < 8; i++) {
        int r = row0 + ty * 8 + i;
        float* trow = g_t + (size_t)r * (NH * CDIM) + (size_t)h * CDIM + col0 + tx * 8;
        ((float4*)trow)[0] = make_float4(acc[i][0], acc[i][1], acc[i][2], acc[i][3]);
        ((float4*)trow)[1] = make_float4(acc[i][4], acc[i][5], acc[i][6], acc[i][7]);
    }
}

// ---------------------------------------------------------------------------
// Fused per-(b,w): scores s[j][h] = x_j . t_h (scaled), causal softmax over j<=last,
// then mix A[h][c] = sum_j p[j][h] * x[j][c]. One block per bw, 512 threads.
#define XS_STRIDE 132
#define TS_STRIDE 130
__global__ __launch_bounds__(512)
void k_attn_fused(const float* __restrict__ x) {
    __shared__ float xs[CSEQ * XS_STRIDE];
    __shared__ float ts[NH * TS_STRIDE];
    __shared__ float S[CSEQ][NH + 1];
    __shared__ float P[CSEQ][NH + 1];

    const int bw   = blockIdx.x;
    const int last = g_last[bw];
    const int tid  = threadIdx.x;
    const float* xbase = x   + (size_t)bw * CSEQ * CDIM;
    const float* tbase = g_t + (size_t)bw * NH * CDIM;

    // ---- phase 1: scores ----
    const int j1 = tid >> 4, h1 = tid & 15;
    float sc = 0.f;
    for (int c0 = 0; c0 < CDIM; c0 += 128) {
        for (int q = tid; q < 1024; q += 512) {
            int jj = q >> 5, cq = (q & 31) * 4;
            *(float4*)&xs[jj * XS_STRIDE + cq] =
                *(const float4*)(xbase + (size_t)jj * CDIM + c0 + cq);
        }
        for (int i = tid; i < 2048; i += 512) {
            int hh = i >> 7, cc = i & 127;
            ts[hh * TS_STRIDE + cc] = tbase[(size_t)hh * CDIM + c0 + cc];
        }
        __syncthreads();
        const float* xr = &xs[j1 * XS_STRIDE];
        const float* tr = &ts[h1 * TS_STRIDE];
        #pragma unroll 8
        for (int c = 0; c < 128; c++) sc = fmaf(xr[c], tr[c], sc);
        __syncthreads();
    }
    S[j1][h1] = sc * 0.125f;   // 1/sqrt(64)
    __syncthreads();

    // ---- phase 2: softmax (warp per head) ----
    {
        const int h = tid >> 5, lane = tid & 31;
        float s = (lane <= last) ? S[lane][h] : -INFINITY;
        float m = s;
        #pragma unroll
        for (int off = 16; off; off >>= 1) m = fmaxf(m, __shfl_xor_sync(0xffffffffu, m, off));
        float e = (lane <= last) ? __expf(s - m) : 0.f;
        float sum = e;
        #pragma unroll
        for (int off = 16; off; off >>= 1) sum += __shfl_xor_sync(0xffffffffu, sum, off);
        P[lane][h] = e / sum;
    }
    __syncthreads();

    // ---- phase 3: mix A[h][c] = sum_j P[j][h] x[j][c] ----
    const int h3 = tid >> 5, cq3 = (tid & 31) * 4;
    float pj[CSEQ];
    #pragma unroll
    for (int jj = 0; jj < CSEQ; jj++) pj[jj] = P[jj][h3];
    float* Arow = g_A + (size_t)bw * NH * CDIM + (size_t)h3 * CDIM;

    for (int c0 = 0; c0 < CDIM; c0 += 128) {
        for (int q = tid; q < 1024; q += 512) {
            int jj = q >> 5, cq = (q & 31) * 4;
            *(float4*)&xs[jj * XS_STRIDE + cq] =
                *(const float4*)(xbase + (size_t)jj * CDIM + c0 + cq);
        }
        __syncthreads();
        float4 acc = make_float4(0.f, 0.f, 0.f, 0.f);
        #pragma unroll
        for (int jj = 0; jj < CSEQ; jj++) {
            float4 xv = *(const float4*)&xs[jj * XS_STRIDE + cq3];
            acc.x = fmaf(pj[jj], xv.x, acc.x);
            acc.y = fmaf(pj[jj], xv.y, acc.y);
            acc.z = fmaf(pj[jj], xv.z, acc.z);
            acc.w = fmaf(pj[jj], xv.w, acc.w);
        }
        *(float4*)(Arow + c0 + cq3) = acc;
        __syncthreads();
    }
}

// ---------------------------------------------------------------------------
// O[bw, h*64+n] = sum_c A[bw][h][c] * Wv[c, h*64+n], Wv[c,hn] = attn_w[c*3072 + 2048 + h*64 + n]
// Per head: GEMM M=1024 x N=64 x K=1024.  grid (8 mblk, 16 h), BM=128 BN=64 BK=8.
__global__ __launch_bounds__(256)
void k_ogemm(const float* __restrict__ attn_w) {
    __shared__ float As[8][128];
    __shared__ float Bs[8][64];

    const int h    = blockIdx.y;
    const int row0 = blockIdx.x * 128;
    const int tid  = threadIdx.x;
    const int ty = tid >> 4, tx = tid & 15;

    float acc[8][4];
    #pragma unroll
    for (int i = 0; i < 8; i++)
        #pragma unroll
        for (int j = 0; j < 4; j++) acc[i][j] = 0.f;

    const float* Abase = g_A + (size_t)row0 * (NH * CDIM) + (size_t)h * CDIM;
    const float* Bbase = attn_w + 2 * CDIM + h * HD;

    for (int k0 = 0; k0 < CDIM; k0 += 8) {
        {
            int r = tid >> 1, kq = (tid & 1) * 4;
            float4 v = *(const float4*)(Abase + (size_t)r * (NH * CDIM) + k0 + kq);
            As[kq + 0][r] = v.x; As[kq + 1][r] = v.y; As[kq + 2][r] = v.z; As[kq + 3][r] = v.w;
        }
        if (tid < 128) {
            int k = tid >> 4, nq = (tid & 15) * 4;
            *(float4*)&Bs[k][nq] = *(const float4*)(Bbase + (size_t)(k0 + k) * 3072 + nq);
        }
        __syncthreads();

        #pragma unroll
        for (int kk = 0; kk < 8; kk++) {
            float a[8], b[4];
            #pragma unroll
            for (int i = 0; i < 8; i++) a[i] = As[kk][ty * 8 + i];
            #pragma unroll
            for (int j = 0; j < 4; j++) b[j] = Bs[kk][tx * 4 + j];
            #pragma unroll
            for (int i = 0; i < 8; i++)
                #pragma unroll
                for (int j = 0; j < 4; j++)
                    acc[i][j] = fmaf(a[i], b[j], acc[i][j]);
        }
        __syncthreads();
    }

    #pragma unroll
    for (int i = 0; i < 8; i++) {
        int r = row0 + ty * 8 + i;
        *(float4*)(g_o + (size_t)r * CDIM + h * HD + tx * 4) =
            make_float4(acc[i][0], acc[i][1], acc[i][2], acc[i][3]);
    }
}

// ---------------------------------------------------------------------------
extern "C" void kernel_launch(void* const* d_in, const int* in_sizes, int n_in,
                              void* d_out, int out_size) {
    const float* x      = (const float*)d_in[0];  // (4,256,32,1024)
    const int*   mask   = (const int*)  d_in[1];  // (4,256,32)
    const float* pos    = (const float*)d_in[2];  // (256,1024)
    const float* attn_w = (const float*)d_in[3];  // (1024,3072)
    const float* proj_w = (const float*)d_in[4];  // (1024,1024)
    float*       out    = (float*)d_out;          // (4,256,1024)

    float* qb; cudaGetSymbolAddress((void**)&qb, g_q);
    float* ob; cudaGetSymbolAddress((void**)&ob, g_o);

    // 1) last index per (b,w)
    k_last<<<4, 256>>>(mask);

    // 2) Q for gathered rows only: [1024,1024] = gather(x) @ attn_w[:, :1024]
    {
        dim3 grid(CDIM / 128, BW / 128);
        sgemm<1><<<grid, 256>>>(x, attn_w, qb, CDIM, CDIM, 3 * CDIM, CDIM, nullptr);
    }

    // 3) t[bw][h][:] = Wk_h @ q_h   (batched GEMM K=64)
    {
        dim3 grid(CDIM / 128, BW / 128, NH);
        k_tgemm<<<grid, 256>>>(attn_w);
    }

    // 4) fused scores + softmax + mix over raw x
    k_attn_fused<<<BW, 512>>>(x);

    // 5) O = A_h @ Wv_h per head
    {
        dim3 grid(BW / 128, NH);
        k_ogemm<<<grid, 256>>>(attn_w);
    }

    // 6) out = (O + pos_emb) @ proj_w
    {
        dim3 grid(CDIM / 128, BW / 128);
        sgemm<2><<<grid, 256>>>(ob, proj_w, out, CDIM, CDIM, CDIM, CDIM, pos);
    }
}

// round 3
// speedup vs baseline: 6.5619x; 1.5330x over previous
#include <cuda_runtime.h>
#include <cstdint>
#include <math.h>

#define BB   4
#define WW   256
#define CSEQ 32
#define CDIM 1024
#define NH   16
#define HD   64
#define BW   1024

typedef unsigned long long ull;

// Scratch (device globals: allocation-free rule)
__device__ float g_q [(size_t)BW * CDIM];
__device__ float g_t [(size_t)BW * NH * CDIM];
__device__ float g_A [(size_t)BW * NH * CDIM];
__device__ float g_o [(size_t)BW * CDIM];
__device__ int   g_last[BW];

// ---- packed fp32 helpers (FFMA2) --------------------------------------
__device__ __forceinline__ void ffma2(ull& d, ull a, ull b) {
    asm("fma.rn.f32x2 %0, %1, %2, %3;" : "=l"(d) : "l"(a), "l"(b), "l"(d));
}
__device__ __forceinline__ ull pack2(float x) {
    ull r; asm("mov.b64 %0, {%1, %1};" : "=l"(r) : "f"(x)); return r;
}
__device__ __forceinline__ ull pack2f(float x, float y) {
    ull r; asm("mov.b64 %0, {%1, %2};" : "=l"(r) : "f"(x), "f"(y)); return r;
}
__device__ __forceinline__ float2 unpack2(ull v) {
    float2 f; asm("mov.b64 {%0, %1}, %2;" : "=f"(f.x), "=f"(f.y) : "l"(v)); return f;
}

// ---------------------------------------------------------------------------
__global__ void k_last(const int* __restrict__ mask) {
    int i = blockIdx.x * blockDim.x + threadIdx.x;
    if (i < BW) {
        int s = 0;
        #pragma unroll
        for (int j = 0; j < CSEQ; j++) s += mask[i * CSEQ + j];
        g_last[i] = s - 1;
    }
}

// ---------------------------------------------------------------------------
// GEMM  C[M,N] = A[M,K] * B[K,N], BM=64 BN=128 BK=16, 256 thr, thread tile 4x8.
// MODE 1: A row m at A + (m*CSEQ + g_last[m])*lda   (gather query row)
// MODE 2: A row m at A + m*lda, plus pos[(m%WW)*CDIM + k]
template <int MODE>
__global__ __launch_bounds__(256)
void gemm_mn(const float* __restrict__ A, const float* __restrict__ B,
             float* __restrict__ C, int lda, int ldb, int ldc,
             const float* __restrict__ pos) {
    __shared__ float As[16][64];
    __shared__ float Bs[16][128];

    const int tid  = threadIdx.x;
    const int row0 = blockIdx.y * 64;
    const int col0 = blockIdx.x * 128;
    const int ty = tid >> 4, tx = tid & 15;

    ull acc[4][4];
    #pragma unroll
    for (int i = 0; i < 4; i++)
        #pragma unroll
        for (int j = 0; j < 4; j++) acc[i][j] = 0ull;

    const int ar = tid >> 2;            // 0..63
    const int ak = (tid & 3) * 4;       // 0,4,8,12
    const int grow = row0 + ar;
    const float* arow;
    if (MODE == 1) arow = A + ((size_t)grow * CSEQ + g_last[grow]) * (size_t)lda;
    else           arow = A + (size_t)grow * (size_t)lda;
    const float* prow = (MODE == 2) ? (pos + (size_t)(grow & (WW - 1)) * CDIM) : nullptr;

    const int bk = tid >> 4;            // 0..15
    const int bn = (tid & 15) * 8;

    for (int k0 = 0; k0 < CDIM; k0 += 16) {
        float4 av = *(const float4*)(arow + k0 + ak);
        if (MODE == 2) {
            const float* pr = prow + k0 + ak;
            av.x += pr[0]; av.y += pr[1]; av.z += pr[2]; av.w += pr[3];
        }
        As[ak + 0][ar] = av.x; As[ak + 1][ar] = av.y;
        As[ak + 2][ar] = av.z; As[ak + 3][ar] = av.w;

        const float* bp = B + (size_t)(k0 + bk) * (size_t)ldb + col0 + bn;
        *(float4*)&Bs[bk][bn]     = *(const float4*)(bp);
        *(float4*)&Bs[bk][bn + 4] = *(const float4*)(bp + 4);
        __syncthreads();

        #pragma unroll
        for (int kk = 0; kk < 16; kk++) {
            float4 a4 = *(const float4*)&As[kk][ty * 4];
            ull a2[4] = {pack2(a4.x), pack2(a4.y), pack2(a4.z), pack2(a4.w)};
            const ull* b2 = (const ull*)&Bs[kk][tx * 8];
            #pragma unroll
            for (int i = 0; i < 4; i++)
                #pragma unroll
                for (int j = 0; j < 4; j++)
                    ffma2(acc[i][j], a2[i], b2[j]);
        }
        __syncthreads();
    }

    #pragma unroll
    for (int i = 0; i < 4; i++) {
        int r = row0 + ty * 4 + i;
        float* cp = C + (size_t)r * (size_t)ldc + col0 + tx * 8;
        float2 u0 = unpack2(acc[i][0]), u1 = unpack2(acc[i][1]);
        float2 u2 = unpack2(acc[i][2]), u3 = unpack2(acc[i][3]);
        ((float4*)cp)[0] = make_float4(u0.x, u0.y, u1.x, u1.y);
        ((float4*)cp)[1] = make_float4(u2.x, u2.y, u3.x, u3.y);
    }
}

// ---------------------------------------------------------------------------
// t[bw][h][c] = sum_d q[bw, h*64+d] * attn_w[c*3072 + 1024 + h*64 + d]
// Per head GEMM M=1024 x N=1024 x K=64. BM=BN=128 BK=16, 256 thr, 8x8 tile.
__global__ __launch_bounds__(256)
void k_tgemm2(const float* __restrict__ attn_w) {
    __shared__ float As[16][128];
    __shared__ float Bs[16][128];

    const int h    = blockIdx.z;
    const int col0 = blockIdx.x * 128;
    const int row0 = blockIdx.y * 128;
    const int tid  = threadIdx.x;
    const int ty = tid >> 4, tx = tid & 15;

    ull acc[8][4];
    #pragma unroll
    for (int i = 0; i < 8; i++)
        #pragma unroll
        for (int j = 0; j < 4; j++) acc[i][j] = 0ull;

    const float* qbase = g_q + (size_t)row0 * CDIM + h * HD;
    const float* wbase = attn_w + (size_t)col0 * 3072 + CDIM + h * HD;

    const int m  = tid >> 1;
    const int kq = (tid & 1) * 8;

    for (int k0 = 0; k0 < HD; k0 += 16) {
        {
            float4 v0 = *(const float4*)(qbase + (size_t)m * CDIM + k0 + kq);
            float4 v1 = *(const float4*)(qbase + (size_t)m * CDIM + k0 + kq + 4);
            As[kq + 0][m] = v0.x; As[kq + 1][m] = v0.y; As[kq + 2][m] = v0.z; As[kq + 3][m] = v0.w;
            As[kq + 4][m] = v1.x; As[kq + 5][m] = v1.y; As[kq + 6][m] = v1.z; As[kq + 7][m] = v1.w;
        }
        {
            float4 v0 = *(const float4*)(wbase + (size_t)m * 3072 + k0 + kq);
            float4 v1 = *(const float4*)(wbase + (size_t)m * 3072 + k0 + kq + 4);
            Bs[kq + 0][m] = v0.x; Bs[kq + 1][m] = v0.y; Bs[kq + 2][m] = v0.z; Bs[kq + 3][m] = v0.w;
            Bs[kq + 4][m] = v1.x; Bs[kq + 5][m] = v1.y; Bs[kq + 6][m] = v1.z; Bs[kq + 7][m] = v1.w;
        }
        __syncthreads();

        #pragma unroll
        for (int kk = 0; kk < 16; kk++) {
            float4 a0 = *(const float4*)&As[kk][ty * 8];
            float4 a1 = *(const float4*)&As[kk][ty * 8 + 4];
            ull a2[8] = {pack2(a0.x), pack2(a0.y), pack2(a0.z), pack2(a0.w),
                         pack2(a1.x), pack2(a1.y), pack2(a1.z), pack2(a1.w)};
            const ull* b2 = (const ull*)&Bs[kk][tx * 8];
            #pragma unroll
            for (int i = 0; i < 8; i++)
                #pragma unroll
                for (int j = 0; j < 4; j++)
                    ffma2(acc[i][j], a2[i], b2[j]);
        }
        __syncthreads();
    }

    #pragma unroll
    for (int i = 0; i < 8; i++) {
        int r = row0 + ty * 8 + i;
        float* trow = g_t + (size_t)r * (NH * CDIM) + (size_t)h * CDIM + col0 + tx * 8;
        float2 u0 = unpack2(acc[i][0]), u1 = unpack2(acc[i][1]);
        float2 u2 = unpack2(acc[i][2]), u3 = unpack2(acc[i][3]);
        ((float4*)trow)[0] = make_float4(u0.x, u0.y, u1.x, u1.y);
        ((float4*)trow)[1] = make_float4(u2.x, u2.y, u3.x, u3.y);
    }
}

// ---------------------------------------------------------------------------
// Fused per-(b,w): x tile resident in smem (read once). 512 threads.
//  phase1: S[j][h] = x_j . t_h   (reg-blocked 4j x 4h, 16-way k-split + shfl reduce)
//  phase2: causal softmax per head (warp per head)
//  phase3: A[h][c] = sum_j P[j][h] x[j][c]  (4h x 8c blocking)
#define XPAD 4
#define XSTR (CDIM + XPAD)                   // 1028
#define OFF_TS (CSEQ * XSTR)                 // 32896
#define OFF_S  (OFF_TS + NH * XSTR)          // 49344
#define OFF_P  (OFF_S + CSEQ * 17)           // 49888
#define SMEM_FLOATS (OFF_P + CSEQ * 17)      // 50432
#define SMEM_BYTES (SMEM_FLOATS * 4)         // 201728

__global__ __launch_bounds__(512)
void k_attn_fused2(const float* __restrict__ x) {
    extern __shared__ float sm[];
    float* xs  = sm;
    float* ts  = sm + OFF_TS;
    float* Ssm = sm + OFF_S;
    float* Psm = sm + OFF_P;

    const int bw   = blockIdx.x;
    const int tid  = threadIdx.x;
    const int last = g_last[bw];

    // ---- load x tile (32x1024) and t tile (16x1024) ----
    const float* xbase = x + (size_t)bw * CSEQ * CDIM;
    #pragma unroll
    for (int q = tid; q < 8192; q += 512) {
        int row = q >> 8, c4 = q & 255;
        *(float4*)&xs[row * XSTR + c4 * 4] = *(const float4*)(xbase + (size_t)row * CDIM + c4 * 4);
    }
    const float* tbase = g_t + (size_t)bw * (NH * CDIM);
    #pragma unroll
    for (int q = tid; q < 4096; q += 512) {
        int row = q >> 8, c4 = q & 255;
        *(float4*)&ts[row * XSTR + c4 * 4] = *(const float4*)(tbase + (size_t)row * CDIM + c4 * 4);
    }
    __syncthreads();

    // ---- phase 1: scores ----
    {
        const int ks = tid & 15;
        const int h0 = ((tid >> 4) & 3) * 4;
        const int j0 = (tid >> 6) * 4;

        ull acc2[4][4];
        #pragma unroll
        for (int a = 0; a < 4; a++)
            #pragma unroll
            for (int b = 0; b < 4; b++) acc2[a][b] = 0ull;

        #pragma unroll
        for (int k = 0; k < 16; k++) {
            const int c = (k * 16 + ks) * 4;
            float4 xv[4], tv[4];
            #pragma unroll
            for (int a = 0; a < 4; a++) xv[a] = *(const float4*)&xs[(j0 + a) * XSTR + c];
            #pragma unroll
            for (int b = 0; b < 4; b++) tv[b] = *(const float4*)&ts[(h0 + b) * XSTR + c];
            #pragma unroll
            for (int a = 0; a < 4; a++) {
                ull xl = pack2f(xv[a].x, xv[a].y), xh = pack2f(xv[a].z, xv[a].w);
                #pragma unroll
                for (int b = 0; b < 4; b++) {
                    ffma2(acc2[a][b], xl, pack2f(tv[b].x, tv[b].y));
                    ffma2(acc2[a][b], xh, pack2f(tv[b].z, tv[b].w));
                }
            }
        }
        // reduce across the 16 k-splits (half-warp) — lane ks keeps (a,b)=(ks>>2,ks&3)
        float out = 0.f;
        #pragma unroll
        for (int a = 0; a < 4; a++)
            #pragma unroll
            for (int b = 0; b < 4; b++) {
                float2 u = unpack2(acc2[a][b]);
                float s = u.x + u.y;
                s += __shfl_xor_sync(0xffffffffu, s, 1);
                s += __shfl_xor_sync(0xffffffffu, s, 2);
                s += __shfl_xor_sync(0xffffffffu, s, 4);
                s += __shfl_xor_sync(0xffffffffu, s, 8);
                if (ks == a * 4 + b) out = s;
            }
        Ssm[(j0 + (ks >> 2)) * 17 + h0 + (ks & 3)] = out * 0.125f;
    }
    __syncthreads();

    // ---- phase 2: softmax (warp per head) ----
    {
        const int h = tid >> 5, lane = tid & 31;
        float s = (lane <= last) ? Ssm[lane * 17 + h] : -INFINITY;
        float m = s;
        #pragma unroll
        for (int off = 16; off; off >>= 1) m = fmaxf(m, __shfl_xor_sync(0xffffffffu, m, off));
        float e = (lane <= last) ? __expf(s - m) : 0.f;
        float sum = e;
        #pragma unroll
        for (int off = 16; off; off >>= 1) sum += __shfl_xor_sync(0xffffffffu, sum, off);
        Psm[lane * 17 + h] = e / sum;
    }
    __syncthreads();

    // ---- phase 3: mix A[h][c] = sum_j P[j][h] x[j][c] ----
    {
        const int h0 = (tid >> 7) * 4;
        const int cg = tid & 127;

        ull acc[4][4];
        #pragma unroll
        for (int b = 0; b < 4; b++)
            #pragma unroll
            for (int q = 0; q < 4; q++) acc[b][q] = 0ull;

        #pragma unroll 8
        for (int j = 0; j < CSEQ; j++) {
            ull p2[4];
            #pragma unroll
            for (int b = 0; b < 4; b++) p2[b] = pack2(Psm[j * 17 + h0 + b]);
            float4 x0 = *(const float4*)&xs[j * XSTR + cg * 8];
            float4 x1 = *(const float4*)&xs[j * XSTR + cg * 8 + 4];
            ull xp[4] = {pack2f(x0.x, x0.y), pack2f(x0.z, x0.w),
                         pack2f(x1.x, x1.y), pack2f(x1.z, x1.w)};
            #pragma unroll
            for (int b = 0; b < 4; b++)
                #pragma unroll
                for (int q = 0; q < 4; q++)
                    ffma2(acc[b][q], p2[b], xp[q]);
        }
        float* Abase = g_A + (size_t)bw * (NH * CDIM);
        #pragma unroll
        for (int b = 0; b < 4; b++) {
            float* dst = Abase + (size_t)(h0 + b) * CDIM + cg * 8;
            float2 u0 = unpack2(acc[b][0]), u1 = unpack2(acc[b][1]);
            float2 u2 = unpack2(acc[b][2]), u3 = unpack2(acc[b][3]);
            ((float4*)dst)[0] = make_float4(u0.x, u0.y, u1.x, u1.y);
            ((float4*)dst)[1] = make_float4(u2.x, u2.y, u3.x, u3.y);
        }
    }
}

// ---------------------------------------------------------------------------
// O[bw, h*64+n] = sum_c A[bw][h][c] * attn_w[c*3072 + 2048 + h*64 + n]
// Per head GEMM M=1024 x N=64 x K=1024. BM=128 BN=64 BK=16, 256 thr, 8x4 tile.
__global__ __launch_bounds__(256)
void k_ogemm2(const float* __restrict__ attn_w) {
    __shared__ float As[16][128];
    __shared__ float Bs[16][64];

    const int h    = blockIdx.y;
    const int row0 = blockIdx.x * 128;
    const int tid  = threadIdx.x;
    const int ty = tid >> 4, tx = tid & 15;

    ull acc[8][2];
    #pragma unroll
    for (int i = 0; i < 8; i++) { acc[i][0] = 0ull; acc[i][1] = 0ull; }

    const float* Abase = attn_w; // placeholder to silence unused warn pattern
    (void)Abase;
    const float* Ab = g_A + (size_t)row0 * (NH * CDIM) + (size_t)h * CDIM;
    const float* Bb = attn_w + 2 * CDIM + h * HD;

    const int r  = tid >> 1;
    const int kq = (tid & 1) * 8;
    const int bk = tid >> 4;
    const int bn = (tid & 15) * 4;

    for (int k0 = 0; k0 < CDIM; k0 += 16) {
        {
            float4 v0 = *(const float4*)(Ab + (size_t)r * (NH * CDIM) + k0 + kq);
            float4 v1 = *(const float4*)(Ab + (size_t)r * (NH * CDIM) + k0 + kq + 4);
            As[kq + 0][r] = v0.x; As[kq + 1][r] = v0.y; As[kq + 2][r] = v0.z; As[kq + 3][r] = v0.w;
            As[kq + 4][r] = v1.x; As[kq + 5][r] = v1.y; As[kq + 6][r] = v1.z; As[kq + 7][r] = v1.w;
        }
        *(float4*)&Bs[bk][bn] = *(const float4*)(Bb + (size_t)(k0 + bk) * 3072 + bn);
        __syncthreads();

        #pragma unroll
        for (int kk = 0; kk < 16; kk++) {
            float4 a0 = *(const float4*)&As[kk][ty * 8];
            float4 a1 = *(const float4*)&As[kk][ty * 8 + 4];
            ull a2[8] = {pack2(a0.x), pack2(a0.y), pack2(a0.z), pack2(a0.w),
                         pack2(a1.x), pack2(a1.y), pack2(a1.z), pack2(a1.w)};
            const ull* b2 = (const ull*)&Bs[kk][tx * 4];
            #pragma unroll
            for (int i = 0; i < 8; i++) {
                ffma2(acc[i][0], a2[i], b2[0]);
                ffma2(acc[i][1], a2[i], b2[1]);
            }
        }
        __syncthreads();
    }

    #pragma unroll
    for (int i = 0; i < 8; i++) {
        int rr = row0 + ty * 8 + i;
        float2 u0 = unpack2(acc[i][0]), u1 = unpack2(acc[i][1]);
        *(float4*)(g_o + (size_t)rr * CDIM + h * HD + tx * 4) =
            make_float4(u0.x, u0.y, u1.x, u1.y);
    }
}

// ---------------------------------------------------------------------------
extern "C" void kernel_launch(void* const* d_in, const int* in_sizes, int n_in,
                              void* d_out, int out_size) {
    const float* x      = (const float*)d_in[0];  // (4,256,32,1024)
    const int*   mask   = (const int*)  d_in[1];  // (4,256,32)
    const float* pos    = (const float*)d_in[2];  // (256,1024)
    const float* attn_w = (const float*)d_in[3];  // (1024,3072)
    const float* proj_w = (const float*)d_in[4];  // (1024,1024)
    float*       out    = (float*)d_out;          // (4,256,1024)

    float* qb; cudaGetSymbolAddress((void**)&qb, g_q);
    float* ob; cudaGetSymbolAddress((void**)&ob, g_o);

    static int smem_set = 0;
    if (!smem_set) {
        cudaFuncSetAttribute(k_attn_fused2, cudaFuncAttributeMaxDynamicSharedMemorySize, SMEM_BYTES);
        smem_set = 1;
    }

    // 1) last index per (b,w)
    k_last<<<4, 256>>>(mask);

    // 2) Q for gathered rows: [1024,1024] = gather(x) @ attn_w[:, :1024]
    {
        dim3 grid(CDIM / 128, BW / 64);   // (8,16) = 128 CTAs
        gemm_mn<1><<<grid, 256>>>(x, attn_w, qb, CDIM, 3 * CDIM, CDIM, nullptr);
    }

    // 3) t[bw][h][:] = Wk_h @ q_h   (batched GEMM K=64)
    {
        dim3 grid(CDIM / 128, BW / 128, NH);
        k_tgemm2<<<grid, 256>>>(attn_w);
    }

    // 4) fused scores + softmax + mix (x resident in smem)
    k_attn_fused2<<<BW, 512, SMEM_BYTES>>>(x);

    // 5) O = A_h @ Wv_h per head
    {
        dim3 grid(BW / 128, NH);
        k_ogemm2<<<grid, 256>>>(attn_w);
    }

    // 6) out = (O + pos_emb) @ proj_w
    {
        dim3 grid(CDIM / 128, BW / 64);   // (8,16)
        gemm_mn<2><<<grid, 256>>>(ob, proj_w, out, CDIM, CDIM, CDIM, pos);
    }
}

// round 5
// speedup vs baseline: 9.9443x; 1.5155x over previous
#include <cuda_runtime.h>
#include <cuda_bf16.h>
#include <cstdint>
#include <math.h>

#define BB   4
#define WW   256
#define CSEQ 32
#define CDIM 1024
#define NH   16
#define HD   64
#define BW   1024

typedef unsigned long long ull;

// Scratch (device globals: allocation-free rule)
__device__ float g_q [(size_t)BW * CDIM];
__device__ float g_t [(size_t)BW * NH * CDIM];
__device__ float g_A [(size_t)BW * NH * CDIM];
__device__ float g_o [(size_t)BW * CDIM];
__device__ float g_BT[3 * (size_t)CDIM * CDIM];   // transposed Wq, proj_w, Wv
__device__ int   g_last[BW];

// ===========================================================================
__device__ __forceinline__ uint32_t smem_to_u32(const void* smem_ptr) {
    uint32_t addr;
    asm("{ .reg .u64 tmp; cvta.to.shared.u64 tmp, %1; cvt.u32.u64 %0, tmp; }"
        : "=r"(addr) : "l"(smem_ptr));
    return addr;
}
#define SMEM_SWIZZLE_128B(byte_offset) ((byte_offset) ^ (((byte_offset) >> 3) & 0x70))

// warp-level bf16 MMA (baseline PTX, no sm_103a feature gate)
__device__ __forceinline__ void mma_bf16(float* d, const uint32_t* a, const uint32_t* b) {
    asm volatile(
        "mma.sync.aligned.m16n8k16.row.col.f32.bf16.bf16.f32 "
        "{%0,%1,%2,%3}, {%4,%5,%6,%7}, {%8,%9}, {%0,%1,%2,%3};"
        : "+f"(d[0]), "+f"(d[1]), "+f"(d[2]), "+f"(d[3])
        : "r"(a[0]), "r"(a[1]), "r"(a[2]), "r"(a[3]), "r"(b[0]), "r"(b[1]));
}
__device__ __forceinline__ void ldsm4(uint32_t* r, uint32_t addr) {
    asm volatile("ldmatrix.sync.aligned.m8n8.x4.shared.b16 {%0,%1,%2,%3}, [%4];"
        : "=r"(r[0]), "=r"(r[1]), "=r"(r[2]), "=r"(r[3]) : "r"(addr));
}

// ---- packed fp32 helpers (FFMA2) --------------------------------------
__device__ __forceinline__ void ffma2(ull& d, ull a, ull b) {
    asm("fma.rn.f32x2 %0, %1, %2, %3;" : "=l"(d) : "l"(a), "l"(b), "l"(d));
}
__device__ __forceinline__ ull pack2(float x) {
    ull r; asm("mov.b64 %0, {%1, %1};" : "=l"(r) : "f"(x)); return r;
}
__device__ __forceinline__ ull pack2f(float x, float y) {
    ull r; asm("mov.b64 %0, {%1, %2};" : "=l"(r) : "f"(x), "f"(y)); return r;
}
__device__ __forceinline__ float2 unpack2(ull v) {
    float2 f; asm("mov.b64 {%0, %1}, %2;" : "=f"(f.x), "=f"(f.y) : "l"(v)); return f;
}

// bf16 hi/lo split + swizzled smem store (4 values = 8 bytes per plane)
__device__ __forceinline__ uint32_t pkbf(__nv_bfloat16 a, __nv_bfloat16 b) {
    return (uint32_t)__bfloat16_as_ushort(a) | ((uint32_t)__bfloat16_as_ushort(b) << 16);
}
__device__ __forceinline__ void split_store(char* hi, char* lo, uint32_t sw, float4 v) {
    __nv_bfloat16 a0 = __float2bfloat16(v.x), a1 = __float2bfloat16(v.y),
                  a2 = __float2bfloat16(v.z), a3 = __float2bfloat16(v.w);
    float r0 = v.x - __bfloat162float(a0), r1 = v.y - __bfloat162float(a1),
          r2 = v.z - __bfloat162float(a2), r3 = v.w - __bfloat162float(a3);
    __nv_bfloat16 b0 = __float2bfloat16(r0), b1 = __float2bfloat16(r1),
                  b2 = __float2bfloat16(r2), b3 = __float2bfloat16(r3);
    *(uint2*)(hi + sw) = make_uint2(pkbf(a0, a1), pkbf(a2, a3));
    *(uint2*)(lo + sw) = make_uint2(pkbf(b0, b1), pkbf(b2, b3));
}

// ---------------------------------------------------------------------------
__global__ void k_last(const int* __restrict__ mask) {
    int i = blockIdx.x * blockDim.x + threadIdx.x;
    if (i < BW) {
        int s = 0;
        #pragma unroll
        for (int j = 0; j < CSEQ; j++) s += mask[i * CSEQ + j];
        g_last[i] = s - 1;
    }
}

// ---------------------------------------------------------------------------
// 1024x1024 fp32 transpose: out[n][k] = in[k*ldin + n]
__global__ __launch_bounds__(256)
void k_transpose(const float* __restrict__ in, int ldin, float* __restrict__ out) {
    __shared__ float t[32][33];
    const int k0 = blockIdx.y * 32, n0 = blockIdx.x * 32;
    const int tx = threadIdx.x, ty = threadIdx.y;
    #pragma unroll
    for (int i = ty; i < 32; i += 8)
        t[i][tx] = in[(size_t)(k0 + i) * ldin + n0 + tx];
    __syncthreads();
    #pragma unroll
    for (int i = ty; i < 32; i += 8)
        out[(size_t)(n0 + i) * CDIM + k0 + tx] = t[tx][i];
}

// ---------------------------------------------------------------------------
// bf16x3 warp-MMA GEMM: C[MTILE x NTILE] per CTA = A(M,K) @ B^T(N,K), fp32 io.
// A rows K-major at Ab + m*lda; B^T rows K-major at Bb + n*ldb.
// MODE 0 plain, 1 gather-A (g_last), 2 pos-add to A. blockIdx.z: head offsets.
// 256 threads = 8 warps (2 m x 4 n), warp tile (MTILE/2) x (NTILE/4).
template <int MTILE, int NTILE, int MODE>
__global__ __launch_bounds__(256)
void gemm_ws(const float* __restrict__ A, int lda, int a_zoff,
             const float* __restrict__ B, int ldb, int b_zoff,
             float* __restrict__ Cc, int ldc, int c_zoff,
             int K, const float* __restrict__ pos) {
    extern __shared__ char dsm[];
    const uint32_t raw = smem_to_u32(dsm);
    const uint32_t padb = (1024u - (raw & 1023u)) & 1023u;
    char* base = dsm + padb;
    const uint32_t sb = raw + padb;
    char* a_hi = base;
    char* a_lo = base + MTILE * 128;
    char* b_hi = base + 2 * MTILE * 128;
    char* b_lo = b_hi + NTILE * 128;
    const uint32_t A_HI = sb, A_LO = sb + MTILE * 128;
    const uint32_t B_HI = sb + 2 * MTILE * 128, B_LO = B_HI + NTILE * 128;

    const int tid = threadIdx.x, wid = tid >> 5, lane = tid & 31;
    const int hz = blockIdx.z;
    const int row0 = blockIdx.y * MTILE, col0 = blockIdx.x * NTILE;
    const float* Ab = A + (size_t)hz * a_zoff;
    const float* Bb = B + (size_t)hz * b_zoff;
    float* Cb = Cc + (size_t)hz * c_zoff;

    constexpr int WM = MTILE / 2, WN = NTILE / 4;
    constexpr int MT = WM / 16, NT = WN / 8;
    const int m_w = (wid >> 2) * WM;
    const int n_w = (wid & 3) * WN;

    float cfr[MT][NT][4];
    #pragma unroll
    for (int i = 0; i < MT; i++)
        #pragma unroll
        for (int j = 0; j < NT; j++)
            #pragma unroll
            for (int q = 0; q < 4; q++) cfr[i][j][q] = 0.f;

    // ldmatrix lane address components
    const int a_row = lane & 15;
    const int a_kb  = (lane >> 4) * 16;
    const int b_row = (lane & 7) + ((lane >> 4) * 8);
    const int b_kb  = ((lane >> 3) & 1) * 16;

    const int nch = K >> 6;
    for (int ch = 0; ch < nch; ch++) {
        const int kbase = ch << 6;
        // ---- stage A (MTILE x 64) as hi/lo bf16 planes ----
        #pragma unroll
        for (int i = 0; i < MTILE / 16; i++) {
            int s = tid + i * 256;
            int r = s >> 4, kq = (s & 15) * 4;
            int grow = row0 + r;
            const float* ap;
            if (MODE == 1)
                ap = Ab + ((size_t)grow * CSEQ + g_last[grow]) * (size_t)lda + kbase + kq;
            else
                ap = Ab + (size_t)grow * (size_t)lda + kbase + kq;
            float4 v = *(const float4*)ap;
            if (MODE == 2) {
                const float* pr = pos + (size_t)(grow & (WW - 1)) * CDIM + kbase + kq;
                v.x += pr[0]; v.y += pr[1]; v.z += pr[2]; v.w += pr[3];
            }
            uint32_t sw = SMEM_SWIZZLE_128B((uint32_t)(r * 128 + kq * 2));
            split_store(a_hi, a_lo, sw, v);
        }
        // ---- stage B (NTILE x 64) ----
        #pragma unroll
        for (int i = 0; i < NTILE / 16; i++) {
            int s = tid + i * 256;
            int r = s >> 4, kq = (s & 15) * 4;
            float4 v = *(const float4*)(Bb + (size_t)(col0 + r) * (size_t)ldb + kbase + kq);
            uint32_t sw = SMEM_SWIZZLE_128B((uint32_t)(r * 128 + kq * 2));
            split_store(b_hi, b_lo, sw, v);
        }
        __syncthreads();

        #pragma unroll
        for (int ks = 0; ks < 4; ks++) {
            const int ksb = ks * 32;
            uint32_t bh[NT][2], bl[NT][2];
            #pragma unroll
            for (int p = 0; p < NT / 2; p++) {
                uint32_t byte = (uint32_t)((n_w + p * 16 + b_row) * 128 + ksb + b_kb);
                uint32_t sw = SMEM_SWIZZLE_128B(byte);
                uint32_t r4[4];
                ldsm4(r4, B_HI + sw);
                bh[2*p][0] = r4[0]; bh[2*p][1] = r4[1];
                bh[2*p+1][0] = r4[2]; bh[2*p+1][1] = r4[3];
                ldsm4(r4, B_LO + sw);
                bl[2*p][0] = r4[0]; bl[2*p][1] = r4[1];
                bl[2*p+1][0] = r4[2]; bl[2*p+1][1] = r4[3];
            }
            uint32_t ah[MT][4], al[MT][4];
            #pragma unroll
            for (int mt = 0; mt < MT; mt++) {
                uint32_t byte = (uint32_t)((m_w + mt * 16 + a_row) * 128 + ksb + a_kb);
                uint32_t sw = SMEM_SWIZZLE_128B(byte);
                ldsm4(ah[mt], A_HI + sw);
                ldsm4(al[mt], A_LO + sw);
            }
            #pragma unroll
            for (int mt = 0; mt < MT; mt++)
                #pragma unroll
                for (int nt = 0; nt < NT; nt++) {
                    mma_bf16(cfr[mt][nt], ah[mt], bh[nt]);
                    mma_bf16(cfr[mt][nt], ah[mt], bl[nt]);
                    mma_bf16(cfr[mt][nt], al[mt], bh[nt]);
                }
        }
        __syncthreads();
    }

    // ---- epilogue: write fragments ----
    #pragma unroll
    for (int mt = 0; mt < MT; mt++) {
        int r0 = row0 + m_w + mt * 16 + (lane >> 2);
        #pragma unroll
        for (int nt = 0; nt < NT; nt++) {
            int c0 = col0 + n_w + nt * 8 + (lane & 3) * 2;
            *(float2*)(Cb + (size_t)r0 * ldc + c0) = make_float2(cfr[mt][nt][0], cfr[mt][nt][1]);
            *(float2*)(Cb + (size_t)(r0 + 8) * ldc + c0) = make_float2(cfr[mt][nt][2], cfr[mt][nt][3]);
        }
    }
}

// ---------------------------------------------------------------------------
// Fused per-(b,w): x tile resident in smem. 1024 threads (32 warps).
#define XPAD 4
#define XSTR (CDIM + XPAD)
#define OFF_TS (CSEQ * XSTR)
#define OFF_S  (OFF_TS + NH * XSTR)
#define OFF_P  (OFF_S + CSEQ * 17)
#define SMEM_FLOATS (OFF_P + CSEQ * 17)
#define SMEM_BYTES (SMEM_FLOATS * 4)

__global__ __launch_bounds__(1024)
void k_attn_fused2(const float* __restrict__ x) {
    extern __shared__ float sm[];
    float* xs  = sm;
    float* ts  = sm + OFF_TS;
    float* Ssm = sm + OFF_S;
    float* Psm = sm + OFF_P;

    const int bw   = blockIdx.x;
    const int tid  = threadIdx.x;
    const int last = g_last[bw];

    const float* xbase = x + (size_t)bw * CSEQ * CDIM;
    #pragma unroll
    for (int q = tid; q < 8192; q += 1024) {
        int row = q >> 8, c4 = q & 255;
        *(float4*)&xs[row * XSTR + c4 * 4] = *(const float4*)(xbase + (size_t)row * CDIM + c4 * 4);
    }
    const float* tbase = g_t + (size_t)bw * (NH * CDIM);
    #pragma unroll
    for (int q = tid; q < 4096; q += 1024) {
        int row = q >> 8, c4 = q & 255;
        *(float4*)&ts[row * XSTR + c4 * 4] = *(const float4*)(tbase + (size_t)row * CDIM + c4 * 4);
    }
    __syncthreads();

    // phase 1: scores. 16-way k-split, 4j x 2h per thread.
    {
        const int ks = tid & 15;
        const int j0 = ((tid >> 4) & 7) * 4;
        const int h0 = (tid >> 7) * 2;

        ull acc2[4][2] = {};
        #pragma unroll
        for (int k = 0; k < 16; k++) {
            const int c = (k * 16 + ks) * 4;
            float4 xv[4], tv[2];
            #pragma unroll
            for (int a = 0; a < 4; a++) xv[a] = *(const float4*)&xs[(j0 + a) * XSTR + c];
            #pragma unroll
            for (int b = 0; b < 2; b++) tv[b] = *(const float4*)&ts[(h0 + b) * XSTR + c];
            #pragma unroll
            for (int a = 0; a < 4; a++) {
                ull xl = pack2f(xv[a].x, xv[a].y), xh = pack2f(xv[a].z, xv[a].w);
                #pragma unroll
                for (int b = 0; b < 2; b++) {
                    ffma2(acc2[a][b], xl, pack2f(tv[b].x, tv[b].y));
                    ffma2(acc2[a][b], xh, pack2f(tv[b].z, tv[b].w));
                }
            }
        }
        float out = 0.f;
        #pragma unroll
        for (int a = 0; a < 4; a++)
            #pragma unroll
            for (int b = 0; b < 2; b++) {
                float2 u = unpack2(acc2[a][b]);
                float s = u.x + u.y;
                s += __shfl_xor_sync(0xffffffffu, s, 1);
                s += __shfl_xor_sync(0xffffffffu, s, 2);
                s += __shfl_xor_sync(0xffffffffu, s, 4);
                s += __shfl_xor_sync(0xffffffffu, s, 8);
                if (ks == a * 2 + b) out = s;
            }
        if (ks < 8)
            Ssm[(j0 + (ks >> 1)) * 17 + h0 + (ks & 1)] = out * 0.125f;
    }
    __syncthreads();

    // phase 2: softmax (warp per head; warps 0-15)
    if (tid < 512) {
        const int h = tid >> 5, lane = tid & 31;
        float s = (lane <= last) ? Ssm[lane * 17 + h] : -INFINITY;
        float m = s;
        #pragma unroll
        for (int off = 16; off; off >>= 1) m = fmaxf(m, __shfl_xor_sync(0xffffffffu, m, off));
        float e = (lane <= last) ? __expf(s - m) : 0.f;
        float sum = e;
        #pragma unroll
        for (int off = 16; off; off >>= 1) sum += __shfl_xor_sync(0xffffffffu, sum, off);
        Psm[lane * 17 + h] = e / sum;
    }
    __syncthreads();

    // phase 3: mix A[h][c] = sum_j P[j][h] x[j][c]  (2h x 8c per thread)
    {
        const int hp = tid >> 7;
        const int cg = tid & 127;

        ull acc[2][4] = {};
        #pragma unroll 8
        for (int j = 0; j < CSEQ; j++) {
            ull p0 = pack2(Psm[j * 17 + hp * 2]);
            ull p1 = pack2(Psm[j * 17 + hp * 2 + 1]);
            float4 x0 = *(const float4*)&xs[j * XSTR + cg * 8];
            float4 x1 = *(const float4*)&xs[j * XSTR + cg * 8 + 4];
            ull xp[4] = {pack2f(x0.x, x0.y), pack2f(x0.z, x0.w),
                         pack2f(x1.x, x1.y), pack2f(x1.z, x1.w)};
            #pragma unroll
            for (int q = 0; q < 4; q++) {
                ffma2(acc[0][q], p0, xp[q]);
                ffma2(acc[1][q], p1, xp[q]);
            }
        }
        float* Abase = g_A + (size_t)bw * (NH * CDIM);
        #pragma unroll
        for (int b = 0; b < 2; b++) {
            float* dst = Abase + (size_t)(hp * 2 + b) * CDIM + cg * 8;
            float2 u0 = unpack2(acc[b][0]), u1 = unpack2(acc[b][1]);
            float2 u2 = unpack2(acc[b][2]), u3 = unpack2(acc[b][3]);
            ((float4*)dst)[0] = make_float4(u0.x, u0.y, u1.x, u1.y);
            ((float4*)dst)[1] = make_float4(u2.x, u2.y, u3.x, u3.y);
        }
    }
}

// ---------------------------------------------------------------------------
extern "C" void kernel_launch(void* const* d_in, const int* in_sizes, int n_in,
                              void* d_out, int out_size) {
    const float* x      = (const float*)d_in[0];  // (4,256,32,1024)
    const int*   mask   = (const int*)  d_in[1];  // (4,256,32)
    const float* pos    = (const float*)d_in[2];  // (256,1024)
    const float* attn_w = (const float*)d_in[3];  // (1024,3072)
    const float* proj_w = (const float*)d_in[4];  // (1024,1024)
    float*       out    = (float*)d_out;          // (4,256,1024)

    float* qb;  cudaGetSymbolAddress((void**)&qb,  g_q);
    float* tb;  cudaGetSymbolAddress((void**)&tb,  g_t);
    float* ab;  cudaGetSymbolAddress((void**)&ab,  g_A);
    float* ob;  cudaGetSymbolAddress((void**)&ob,  g_o);
    float* btb; cudaGetSymbolAddress((void**)&btb, g_BT);
    float* BTq = btb;
    float* BTp = btb + (size_t)CDIM * CDIM;
    float* BTv = btb + 2 * (size_t)CDIM * CDIM;

    const int SM_N128 = 2 * 64 * 128 + 2 * 128 * 128 + 1024;  // 50176
    const int SM_N64  = 2 * 64 * 128 + 2 * 64 * 128 + 1024;   // 33792

    static int attr_set = 0;
    if (!attr_set) {
        cudaFuncSetAttribute(k_attn_fused2, cudaFuncAttributeMaxDynamicSharedMemorySize, SMEM_BYTES);
        cudaFuncSetAttribute(gemm_ws<64, 128, 0>, cudaFuncAttributeMaxDynamicSharedMemorySize, SM_N128);
        cudaFuncSetAttribute(gemm_ws<64, 128, 1>, cudaFuncAttributeMaxDynamicSharedMemorySize, SM_N128);
        cudaFuncSetAttribute(gemm_ws<64, 128, 2>, cudaFuncAttributeMaxDynamicSharedMemorySize, SM_N128);
        cudaFuncSetAttribute(gemm_ws<64, 64, 0>,  cudaFuncAttributeMaxDynamicSharedMemorySize, SM_N64);
        attr_set = 1;
    }

    // 1) last index per (b,w)
    k_last<<<4, 256>>>(mask);

    // 2) transposed weight preps: Wq^T, proj^T, Wv^T
    {
        dim3 grid(32, 32), blk(32, 8);
        k_transpose<<<grid, blk>>>(attn_w, 3 * CDIM, BTq);
        k_transpose<<<grid, blk>>>(proj_w, CDIM, BTp);
        k_transpose<<<grid, blk>>>(attn_w + 2 * CDIM, 3 * CDIM, BTv);
    }

    // 3) Q = gather(x) @ Wq   [1024 x 1024 x 1024]
    {
        dim3 grid(8, 16, 1);
        gemm_ws<64, 128, 1><<<grid, 256, SM_N128>>>(x, CDIM, 0, BTq, CDIM, 0,
                                                    qb, CDIM, 0, CDIM, nullptr);
    }

    // 4) t[bw][h] = q_h @ Wk_h^T   [per head: 1024 x 1024 x 64]
    {
        dim3 grid(8, 16, NH);
        gemm_ws<64, 128, 0><<<grid, 256, SM_N128>>>(qb, CDIM, HD,
                                                    attn_w + CDIM, 3 * CDIM, HD,
                                                    tb, NH * CDIM, CDIM, HD, nullptr);
    }

    // 5) fused scores + softmax + mix
    k_attn_fused2<<<BW, 1024, SMEM_BYTES>>>(x);

    // 6) O_h = A_h @ Wv_h   [per head: 1024 x 64 x 1024]
    {
        dim3 grid(1, 16, NH);
        gemm_ws<64, 64, 0><<<grid, 256, SM_N64>>>(ab, NH * CDIM, CDIM,
                                                  BTv, CDIM, HD * CDIM,
                                                  ob, CDIM, HD, CDIM, nullptr);
    }

    // 7) out = (O + pos) @ proj_w   [1024 x 1024 x 1024]
    {
        dim3 grid(8, 16, 1);
        gemm_ws<64, 128, 2><<<grid, 256, SM_N128>>>(ob, CDIM, 0, BTp, CDIM, 0,
                                                    out, CDIM, 0, CDIM, pos);
    }
}

// round 6
// speedup vs baseline: 11.0339x; 1.1096x over previous
#include <cuda_runtime.h>
#include <cuda_bf16.h>
#include <cstdint>
#include <math.h>

#define BB   4
#define WW   256
#define CSEQ 32
#define CDIM 1024
#define NH   16
#define HD   64
#define BW   1024

typedef unsigned long long ull;

// Scratch (device globals: allocation-free rule)
__device__ float g_q [(size_t)BW * CDIM];
__device__ float g_t [(size_t)BW * NH * CDIM];
__device__ float g_A [(size_t)BW * NH * CDIM];
__device__ float g_o [(size_t)BW * CDIM];
__device__ float g_BT[3 * (size_t)CDIM * CDIM];   // transposed Wq, proj_w, Wv
__device__ int   g_last[BW];

// ===========================================================================
__device__ __forceinline__ uint32_t smem_to_u32(const void* smem_ptr) {
    uint32_t addr;
    asm("{ .reg .u64 tmp; cvta.to.shared.u64 tmp, %1; cvt.u32.u64 %0, tmp; }"
        : "=r"(addr) : "l"(smem_ptr));
    return addr;
}
#define SMEM_SWIZZLE_128B(byte_offset) ((byte_offset) ^ (((byte_offset) >> 3) & 0x70))

__device__ __forceinline__ void mma_bf16(float* d, const uint32_t* a, const uint32_t* b) {
    asm volatile(
        "mma.sync.aligned.m16n8k16.row.col.f32.bf16.bf16.f32 "
        "{%0,%1,%2,%3}, {%4,%5,%6,%7}, {%8,%9}, {%0,%1,%2,%3};"
        : "+f"(d[0]), "+f"(d[1]), "+f"(d[2]), "+f"(d[3])
        : "r"(a[0]), "r"(a[1]), "r"(a[2]), "r"(a[3]), "r"(b[0]), "r"(b[1]));
}
__device__ __forceinline__ void ldsm4(uint32_t* r, uint32_t addr) {
    asm volatile("ldmatrix.sync.aligned.m8n8.x4.shared.b16 {%0,%1,%2,%3}, [%4];"
        : "=r"(r[0]), "=r"(r[1]), "=r"(r[2]), "=r"(r[3]) : "r"(addr));
}
__device__ __forceinline__ void cpa16(uint32_t dst, const void* src) {
    asm volatile("cp.async.cg.shared.global [%0], [%1], 16;" :: "r"(dst), "l"(src));
}
#define CP_COMMIT()  asm volatile("cp.async.commit_group;" ::: "memory")
#define CP_WAIT(n)   asm volatile("cp.async.wait_group %0;" :: "n"(n) : "memory")

// ---- packed fp32 helpers (FFMA2) --------------------------------------
__device__ __forceinline__ void ffma2(ull& d, ull a, ull b) {
    asm("fma.rn.f32x2 %0, %1, %2, %3;" : "=l"(d) : "l"(a), "l"(b), "l"(d));
}
__device__ __forceinline__ ull pack2(float x) {
    ull r; asm("mov.b64 %0, {%1, %1};" : "=l"(r) : "f"(x)); return r;
}
__device__ __forceinline__ ull pack2f(float x, float y) {
    ull r; asm("mov.b64 %0, {%1, %2};" : "=l"(r) : "f"(x), "f"(y)); return r;
}
__device__ __forceinline__ float2 unpack2(ull v) {
    float2 f; asm("mov.b64 {%0, %1}, %2;" : "=f"(f.x), "=f"(f.y) : "l"(v)); return f;
}

// bf16 hi/lo split + swizzled smem store
__device__ __forceinline__ uint32_t pkbf(__nv_bfloat16 a, __nv_bfloat16 b) {
    return (uint32_t)__bfloat16_as_ushort(a) | ((uint32_t)__bfloat16_as_ushort(b) << 16);
}
__device__ __forceinline__ void split_store(char* hi, char* lo, uint32_t sw, float4 v) {
    __nv_bfloat16 a0 = __float2bfloat16(v.x), a1 = __float2bfloat16(v.y),
                  a2 = __float2bfloat16(v.z), a3 = __float2bfloat16(v.w);
    float r0 = v.x - __bfloat162float(a0), r1 = v.y - __bfloat162float(a1),
          r2 = v.z - __bfloat162float(a2), r3 = v.w - __bfloat162float(a3);
    __nv_bfloat16 b0 = __float2bfloat16(r0), b1 = __float2bfloat16(r1),
                  b2 = __float2bfloat16(r2), b3 = __float2bfloat16(r3);
    *(uint2*)(hi + sw) = make_uint2(pkbf(a0, a1), pkbf(a2, a3));
    *(uint2*)(lo + sw) = make_uint2(pkbf(b0, b1), pkbf(b2, b3));
}

// ---------------------------------------------------------------------------
__global__ void k_last(const int* __restrict__ mask) {
    int i = blockIdx.x * blockDim.x + threadIdx.x;
    if (i < BW) {
        int s = 0;
        #pragma unroll
        for (int j = 0; j < CSEQ; j++) s += mask[i * CSEQ + j];
        g_last[i] = s - 1;
    }
}

// ---------------------------------------------------------------------------
__global__ __launch_bounds__(256)
void k_transpose(const float* __restrict__ in, int ldin, float* __restrict__ out) {
    __shared__ float t[32][33];
    const int k0 = blockIdx.y * 32, n0 = blockIdx.x * 32;
    const int tx = threadIdx.x, ty = threadIdx.y;
    #pragma unroll
    for (int i = ty; i < 32; i += 8)
        t[i][tx] = in[(size_t)(k0 + i) * ldin + n0 + tx];
    __syncthreads();
    #pragma unroll
    for (int i = ty; i < 32; i += 8)
        out[(size_t)(n0 + i) * CDIM + k0 + tx] = t[tx][i];
}

// ---------------------------------------------------------------------------
// bf16x3 warp-MMA GEMM with register-prefetch pipeline.
// C[MTILE x NTILE] per CTA = A(M,K) @ B^T(N,K), fp32 io.
// MODE 0 plain, 1 gather-A (g_last), 2 pos-add to A. blockIdx.z: head offsets.
template <int MTILE, int NTILE, int MODE>
__global__ __launch_bounds__(256)
void gemm_ws(const float* __restrict__ A, int lda, int a_zoff,
             const float* __restrict__ B, int ldb, int b_zoff,
             float* __restrict__ Cc, int ldc, int c_zoff,
             int K, const float* __restrict__ pos) {
    extern __shared__ char dsm[];
    const uint32_t raw = smem_to_u32(dsm);
    const uint32_t padb = (1024u - (raw & 1023u)) & 1023u;
    char* base = dsm + padb;
    const uint32_t sb = raw + padb;
    char* a_hi = base;
    char* a_lo = base + MTILE * 128;
    char* b_hi = base + 2 * MTILE * 128;
    char* b_lo = b_hi + NTILE * 128;
    const uint32_t A_HI = sb, A_LO = sb + MTILE * 128;
    const uint32_t B_HI = sb + 2 * MTILE * 128, B_LO = B_HI + NTILE * 128;

    const int tid = threadIdx.x, wid = tid >> 5, lane = tid & 31;
    const int hz = blockIdx.z;
    const int row0 = blockIdx.y * MTILE, col0 = blockIdx.x * NTILE;
    const float* Ab = A + (size_t)hz * a_zoff;
    const float* Bb = B + (size_t)hz * b_zoff;
    float* Cb = Cc + (size_t)hz * c_zoff;

    constexpr int WM = MTILE / 2, WN = NTILE / 4;
    constexpr int MT = WM / 16, NT = WN / 8;
    constexpr int AIT = MTILE / 16, BIT = NTILE / 16;
    const int m_w = (wid >> 2) * WM;
    const int n_w = (wid & 3) * WN;

    float cfr[MT][NT][4];
    #pragma unroll
    for (int i = 0; i < MT; i++)
        #pragma unroll
        for (int j = 0; j < NT; j++)
            #pragma unroll
            for (int q = 0; q < 4; q++) cfr[i][j][q] = 0.f;

    // hoisted staging pointers + swizzled dst offsets
    const float* aptr[AIT]; const float* pptr[AIT]; const float* bptr[BIT];
    uint32_t aswz[AIT], bswz[BIT];
    #pragma unroll
    for (int i = 0; i < AIT; i++) {
        int s = tid + i * 256;
        int r = s >> 4, kq = (s & 15) * 4;
        int grow = row0 + r;
        if (MODE == 1)
            aptr[i] = Ab + ((size_t)grow * CSEQ + g_last[grow]) * (size_t)lda + kq;
        else
            aptr[i] = Ab + (size_t)grow * (size_t)lda + kq;
        pptr[i] = (MODE == 2) ? (pos + (size_t)(grow & (WW - 1)) * CDIM + kq) : nullptr;
        aswz[i] = SMEM_SWIZZLE_128B((uint32_t)(r * 128 + kq * 2));
    }
    #pragma unroll
    for (int i = 0; i < BIT; i++) {
        int s = tid + i * 256;
        int r = s >> 4, kq = (s & 15) * 4;
        bptr[i] = Bb + (size_t)(col0 + r) * (size_t)ldb + kq;
        bswz[i] = SMEM_SWIZZLE_128B((uint32_t)(r * 128 + kq * 2));
    }

    const int a_row = lane & 15;
    const int a_kb  = (lane >> 4) * 16;
    const int b_row = (lane & 7) + ((lane >> 4) * 8);
    const int b_kb  = ((lane >> 3) & 1) * 16;

    float4 ra[AIT], rb[BIT];
    // prologue: load chunk 0
    #pragma unroll
    for (int i = 0; i < AIT; i++) {
        ra[i] = *(const float4*)(aptr[i]);
        if (MODE == 2) {
            const float* pr = pptr[i];
            ra[i].x += pr[0]; ra[i].y += pr[1]; ra[i].z += pr[2]; ra[i].w += pr[3];
        }
    }
    #pragma unroll
    for (int i = 0; i < BIT; i++) rb[i] = *(const float4*)(bptr[i]);

    const int nch = K >> 6;
    for (int ch = 0; ch < nch; ch++) {
        // store current chunk's regs to smem planes
        #pragma unroll
        for (int i = 0; i < AIT; i++) split_store(a_hi, a_lo, aswz[i], ra[i]);
        #pragma unroll
        for (int i = 0; i < BIT; i++) split_store(b_hi, b_lo, bswz[i], rb[i]);
        __syncthreads();

        // prefetch next chunk (overlaps with ldmatrix + MMA below)
        if (ch + 1 < nch) {
            const int kb = (ch + 1) << 6;
            #pragma unroll
            for (int i = 0; i < AIT; i++) {
                ra[i] = *(const float4*)(aptr[i] + kb);
                if (MODE == 2) {
                    const float* pr = pptr[i] + kb;
                    ra[i].x += pr[0]; ra[i].y += pr[1]; ra[i].z += pr[2]; ra[i].w += pr[3];
                }
            }
            #pragma unroll
            for (int i = 0; i < BIT; i++) rb[i] = *(const float4*)(bptr[i] + kb);
        }

        #pragma unroll
        for (int ks = 0; ks < 4; ks++) {
            const int ksb = ks * 32;
            uint32_t bh[NT][2], bl[NT][2];
            #pragma unroll
            for (int p = 0; p < NT / 2; p++) {
                uint32_t byte = (uint32_t)((n_w + p * 16 + b_row) * 128 + ksb + b_kb);
                uint32_t sw = SMEM_SWIZZLE_128B(byte);
                uint32_t r4[4];
                ldsm4(r4, B_HI + sw);
                bh[2*p][0] = r4[0]; bh[2*p][1] = r4[1];
                bh[2*p+1][0] = r4[2]; bh[2*p+1][1] = r4[3];
                ldsm4(r4, B_LO + sw);
                bl[2*p][0] = r4[0]; bl[2*p][1] = r4[1];
                bl[2*p+1][0] = r4[2]; bl[2*p+1][1] = r4[3];
            }
            uint32_t ah[MT][4], al[MT][4];
            #pragma unroll
            for (int mt = 0; mt < MT; mt++) {
                uint32_t byte = (uint32_t)((m_w + mt * 16 + a_row) * 128 + ksb + a_kb);
                uint32_t sw = SMEM_SWIZZLE_128B(byte);
                ldsm4(ah[mt], A_HI + sw);
                ldsm4(al[mt], A_LO + sw);
            }
            #pragma unroll
            for (int mt = 0; mt < MT; mt++)
                #pragma unroll
                for (int nt = 0; nt < NT; nt++) {
                    mma_bf16(cfr[mt][nt], ah[mt], bh[nt]);
                    mma_bf16(cfr[mt][nt], ah[mt], bl[nt]);
                    mma_bf16(cfr[mt][nt], al[mt], bh[nt]);
                }
        }
        __syncthreads();
    }

    #pragma unroll
    for (int mt = 0; mt < MT; mt++) {
        int r0 = row0 + m_w + mt * 16 + (lane >> 2);
        #pragma unroll
        for (int nt = 0; nt < NT; nt++) {
            int c0 = col0 + n_w + nt * 8 + (lane & 3) * 2;
            *(float2*)(Cb + (size_t)r0 * ldc + c0) = make_float2(cfr[mt][nt][0], cfr[mt][nt][1]);
            *(float2*)(Cb + (size_t)(r0 + 8) * ldc + c0) = make_float2(cfr[mt][nt][2], cfr[mt][nt][3]);
        }
    }
}

// ---------------------------------------------------------------------------
// Fused per-(b,w), cp.async pipelined over 8 c-chunks of 128.
// smem: xs full 32 x 1028 (resident), ts double-buffered 2 x 16 x 132, S/P.
#define XSTR 1028
#define TSTR 132
#define OFF_TS (CSEQ * XSTR)                         // 32896
#define OFF_S  (OFF_TS + 2 * NH * TSTR)              // 37120
#define OFF_P  (OFF_S + CSEQ * 17)                   // 37664
#define SMEM_FLOATS (OFF_P + CSEQ * 17)              // 38208
#define SMEM_BYTES (SMEM_FLOATS * 4)                 // 152832

__global__ __launch_bounds__(1024)
void k_attn_fused3(const float* __restrict__ x) {
    extern __shared__ float sm[];
    float* xs  = sm;
    float* Ssm = sm + OFF_S;
    float* Psm = sm + OFF_P;
    const uint32_t sbase = smem_to_u32(sm);
    const uint32_t XS_U = sbase;
    const uint32_t TS_U = sbase + OFF_TS * 4;

    const int bw   = blockIdx.x;
    const int tid  = threadIdx.x;
    const int last = g_last[bw];
    const float* xbase = x   + (size_t)bw * CSEQ * CDIM;
    const float* tbase = g_t + (size_t)bw * (NH * CDIM);

    // per-thread load slots
    const int xr = tid >> 5, xg = tid & 31;               // x: 32 rows x 32 f4
    const int tr = (tid >> 5) & 15, tg = tid & 31;        // t: 16 rows x 32 f4 (tid<512)

    // issue chunk 0
    {
        cpa16(XS_U + (uint32_t)(xr * XSTR + xg * 4) * 4, xbase + (size_t)xr * CDIM + xg * 4);
        if (tid < 512)
            cpa16(TS_U + (uint32_t)(tr * TSTR + tg * 4) * 4, tbase + (size_t)tr * CDIM + tg * 4);
        CP_COMMIT();
    }

    // phase-1 thread mapping
    const int ks = tid & 15;
    const int j0 = ((tid >> 4) & 7) * 4;
    const int h0 = (tid >> 7) * 2;
    ull acc2[4][2] = {};

    #pragma unroll
    for (int ch = 0; ch < 8; ch++) {
        // issue chunk ch+1
        if (ch + 1 < 8) {
            const int cb = (ch + 1) * 128;
            const int tbuf = (ch + 1) & 1;
            cpa16(XS_U + (uint32_t)(xr * XSTR + cb + xg * 4) * 4,
                  xbase + (size_t)xr * CDIM + cb + xg * 4);
            if (tid < 512)
                cpa16(TS_U + (uint32_t)((tbuf * NH + tr) * TSTR + tg * 4) * 4,
                      tbase + (size_t)tr * CDIM + cb + tg * 4);
            CP_COMMIT();
            CP_WAIT(1);
        } else {
            CP_WAIT(0);
        }
        __syncthreads();

        // partial scores on chunk ch
        const float* tsb = sm + OFF_TS + (ch & 1) * NH * TSTR;
        #pragma unroll
        for (int k = 0; k < 2; k++) {
            const int g = k * 16 + ks;                 // 0..31 within chunk
            const int cx = ch * 128 + g * 4;
            const int ct = g * 4;
            float4 xv[4], tv[2];
            #pragma unroll
            for (int a = 0; a < 4; a++) xv[a] = *(const float4*)&xs[(j0 + a) * XSTR + cx];
            #pragma unroll
            for (int b = 0; b < 2; b++) tv[b] = *(const float4*)&tsb[(h0 + b) * TSTR + ct];
            #pragma unroll
            for (int a = 0; a < 4; a++) {
                ull xl = pack2f(xv[a].x, xv[a].y), xh = pack2f(xv[a].z, xv[a].w);
                #pragma unroll
                for (int b = 0; b < 2; b++) {
                    ffma2(acc2[a][b], xl, pack2f(tv[b].x, tv[b].y));
                    ffma2(acc2[a][b], xh, pack2f(tv[b].z, tv[b].w));
                }
            }
        }
        __syncthreads();
    }

    // reduce 16-way k-split within half-warps
    {
        float out = 0.f;
        #pragma unroll
        for (int a = 0; a < 4; a++)
            #pragma unroll
            for (int b = 0; b < 2; b++) {
                float2 u = unpack2(acc2[a][b]);
                float s = u.x + u.y;
                s += __shfl_xor_sync(0xffffffffu, s, 1);
                s += __shfl_xor_sync(0xffffffffu, s, 2);
                s += __shfl_xor_sync(0xffffffffu, s, 4);
                s += __shfl_xor_sync(0xffffffffu, s, 8);
                if (ks == a * 2 + b) out = s;
            }
        if (ks < 8)
            Ssm[(j0 + (ks >> 1)) * 17 + h0 + (ks & 1)] = out * 0.125f;
    }
    __syncthreads();

    // softmax (warp per head; warps 0-15)
    if (tid < 512) {
        const int h = tid >> 5, lane = tid & 31;
        float s = (lane <= last) ? Ssm[lane * 17 + h] : -INFINITY;
        float m = s;
        #pragma unroll
        for (int off = 16; off; off >>= 1) m = fmaxf(m, __shfl_xor_sync(0xffffffffu, m, off));
        float e = (lane <= last) ? __expf(s - m) : 0.f;
        float sum = e;
        #pragma unroll
        for (int off = 16; off; off >>= 1) sum += __shfl_xor_sync(0xffffffffu, sum, off);
        Psm[lane * 17 + h] = e / sum;
    }
    __syncthreads();

    // phase 3: mix A[h][c] = sum_j P[j][h] x[j][c]  (2h x 8c per thread)
    {
        const int hp = tid >> 7;
        const int cg = tid & 127;

        ull acc[2][4] = {};
        #pragma unroll 8
        for (int j = 0; j < CSEQ; j++) {
            ull p0 = pack2(Psm[j * 17 + hp * 2]);
            ull p1 = pack2(Psm[j * 17 + hp * 2 + 1]);
            float4 x0 = *(const float4*)&xs[j * XSTR + cg * 8];
            float4 x1 = *(const float4*)&xs[j * XSTR + cg * 8 + 4];
            ull xp[4] = {pack2f(x0.x, x0.y), pack2f(x0.z, x0.w),
                         pack2f(x1.x, x1.y), pack2f(x1.z, x1.w)};
            #pragma unroll
            for (int q = 0; q < 4; q++) {
                ffma2(acc[0][q], p0, xp[q]);
                ffma2(acc[1][q], p1, xp[q]);
            }
        }
        float* Abase = g_A + (size_t)bw * (NH * CDIM);
        #pragma unroll
        for (int b = 0; b < 2; b++) {
            float* dst = Abase + (size_t)(hp * 2 + b) * CDIM + cg * 8;
            float2 u0 = unpack2(acc[b][0]), u1 = unpack2(acc[b][1]);
            float2 u2 = unpack2(acc[b][2]), u3 = unpack2(acc[b][3]);
            ((float4*)dst)[0] = make_float4(u0.x, u0.y, u1.x, u1.y);
            ((float4*)dst)[1] = make_float4(u2.x, u2.y, u3.x, u3.y);
        }
    }
}

// ---------------------------------------------------------------------------
extern "C" void kernel_launch(void* const* d_in, const int* in_sizes, int n_in,
                              void* d_out, int out_size) {
    const float* x      = (const float*)d_in[0];  // (4,256,32,1024)
    const int*   mask   = (const int*)  d_in[1];  // (4,256,32)
    const float* pos    = (const float*)d_in[2];  // (256,1024)
    const float* attn_w = (const float*)d_in[3];  // (1024,3072)
    const float* proj_w = (const float*)d_in[4];  // (1024,1024)
    float*       out    = (float*)d_out;          // (4,256,1024)

    float* qb;  cudaGetSymbolAddress((void**)&qb,  g_q);
    float* tb;  cudaGetSymbolAddress((void**)&tb,  g_t);
    float* ab;  cudaGetSymbolAddress((void**)&ab,  g_A);
    float* ob;  cudaGetSymbolAddress((void**)&ob,  g_o);
    float* btb; cudaGetSymbolAddress((void**)&btb, g_BT);
    float* BTq = btb;
    float* BTp = btb + (size_t)CDIM * CDIM;
    float* BTv = btb + 2 * (size_t)CDIM * CDIM;

    const int SM_N128 = 2 * 64 * 128 + 2 * 128 * 128 + 1024;  // 50176
    const int SM_N64  = 2 * 64 * 128 + 2 * 64 * 128 + 1024;   // 33792

    static int attr_set = 0;
    if (!attr_set) {
        cudaFuncSetAttribute(k_attn_fused3, cudaFuncAttributeMaxDynamicSharedMemorySize, SMEM_BYTES);
        cudaFuncSetAttribute(gemm_ws<64, 128, 0>, cudaFuncAttributeMaxDynamicSharedMemorySize, SM_N128);
        cudaFuncSetAttribute(gemm_ws<64, 128, 1>, cudaFuncAttributeMaxDynamicSharedMemorySize, SM_N128);
        cudaFuncSetAttribute(gemm_ws<64, 128, 2>, cudaFuncAttributeMaxDynamicSharedMemorySize, SM_N128);
        cudaFuncSetAttribute(gemm_ws<64, 64, 0>,  cudaFuncAttributeMaxDynamicSharedMemorySize, SM_N64);
        attr_set = 1;
    }

    // 1) last index per (b,w)
    k_last<<<4, 256>>>(mask);

    // 2) transposed weight preps: Wq^T, proj^T, Wv^T
    {
        dim3 grid(32, 32), blk(32, 8);
        k_transpose<<<grid, blk>>>(attn_w, 3 * CDIM, BTq);
        k_transpose<<<grid, blk>>>(proj_w, CDIM, BTp);
        k_transpose<<<grid, blk>>>(attn_w + 2 * CDIM, 3 * CDIM, BTv);
    }

    // 3) Q = gather(x) @ Wq   [1024 x 1024 x 1024]
    {
        dim3 grid(8, 16, 1);
        gemm_ws<64, 128, 1><<<grid, 256, SM_N128>>>(x, CDIM, 0, BTq, CDIM, 0,
                                                    qb, CDIM, 0, CDIM, nullptr);
    }

    // 4) t[bw][h] = q_h @ Wk_h^T   [per head: 1024 x 1024 x 64]
    {
        dim3 grid(8, 16, NH);
        gemm_ws<64, 128, 0><<<grid, 256, SM_N128>>>(qb, CDIM, HD,
                                                    attn_w + CDIM, 3 * CDIM, HD,
                                                    tb, NH * CDIM, CDIM, HD, nullptr);
    }

    // 5) fused scores + softmax + mix (cp.async pipelined)
    k_attn_fused3<<<BW, 1024, SMEM_BYTES>>>(x);

    // 6) O_h = A_h @ Wv_h   [per head: 1024 x 64 x 1024]
    {
        dim3 grid(1, 16, NH);
        gemm_ws<64, 64, 0><<<grid, 256, SM_N64>>>(ab, NH * CDIM, CDIM,
                                                  BTv, CDIM, HD * CDIM,
                                                  ob, CDIM, HD, CDIM, nullptr);
    }

    // 7) out = (O + pos) @ proj_w   [1024 x 1024 x 1024]
    {
        dim3 grid(8, 16, 1);
        gemm_ws<64, 128, 2><<<grid, 256, SM_N128>>>(ob, CDIM, 0, BTp, CDIM, 0,
                                                    out, CDIM, 0, CDIM, pos);
    }
}

// round 7
// speedup vs baseline: 11.3685x; 1.0303x over previous
#include <cuda_runtime.h>
#include <cuda_bf16.h>
#include <cstdint>
#include <math.h>

#define BB   4
#define WW   256
#define CSEQ 32
#define CDIM 1024
#define NH   16
#define HD   64
#define BW   1024

typedef unsigned long long ull;

// Scratch (device globals: allocation-free rule)
__device__ float g_q [(size_t)BW * CDIM];
__device__ float g_t [(size_t)BW * NH * CDIM];
__device__ float g_A [(size_t)BW * NH * CDIM];
__device__ float g_o [(size_t)BW * CDIM];
__device__ float g_BT[3 * (size_t)CDIM * CDIM];   // transposed Wq, proj_w, Wv
__device__ int   g_last[BW];

// ===========================================================================
__device__ __forceinline__ uint32_t smem_to_u32(const void* smem_ptr) {
    uint32_t addr;
    asm("{ .reg .u64 tmp; cvta.to.shared.u64 tmp, %1; cvt.u32.u64 %0, tmp; }"
        : "=r"(addr) : "l"(smem_ptr));
    return addr;
}
#define SMEM_SWIZZLE_128B(byte_offset) ((byte_offset) ^ (((byte_offset) >> 3) & 0x70))

__device__ __forceinline__ void mma_bf16(float* d, const uint32_t* a, const uint32_t* b) {
    asm volatile(
        "mma.sync.aligned.m16n8k16.row.col.f32.bf16.bf16.f32 "
        "{%0,%1,%2,%3}, {%4,%5,%6,%7}, {%8,%9}, {%0,%1,%2,%3};"
        : "+f"(d[0]), "+f"(d[1]), "+f"(d[2]), "+f"(d[3])
        : "r"(a[0]), "r"(a[1]), "r"(a[2]), "r"(a[3]), "r"(b[0]), "r"(b[1]));
}
__device__ __forceinline__ void ldsm4(uint32_t* r, uint32_t addr) {
    asm volatile("ldmatrix.sync.aligned.m8n8.x4.shared.b16 {%0,%1,%2,%3}, [%4];"
        : "=r"(r[0]), "=r"(r[1]), "=r"(r[2]), "=r"(r[3]) : "r"(addr));
}
__device__ __forceinline__ void cpa16(uint32_t dst, const void* src) {
    asm volatile("cp.async.cg.shared.global [%0], [%1], 16;" :: "r"(dst), "l"(src));
}
#define CP_COMMIT()  asm volatile("cp.async.commit_group;" ::: "memory")
#define CP_WAIT(n)   asm volatile("cp.async.wait_group %0;" :: "n"(n) : "memory")

// ---- packed fp32 helpers (FFMA2) --------------------------------------
__device__ __forceinline__ void ffma2(ull& d, ull a, ull b) {
    asm("fma.rn.f32x2 %0, %1, %2, %3;" : "=l"(d) : "l"(a), "l"(b), "l"(d));
}
__device__ __forceinline__ ull pack2(float x) {
    ull r; asm("mov.b64 %0, {%1, %1};" : "=l"(r) : "f"(x)); return r;
}
__device__ __forceinline__ ull pack2f(float x, float y) {
    ull r; asm("mov.b64 %0, {%1, %2};" : "=l"(r) : "f"(x), "f"(y)); return r;
}
__device__ __forceinline__ float2 unpack2(ull v) {
    float2 f; asm("mov.b64 {%0, %1}, %2;" : "=f"(f.x), "=f"(f.y) : "l"(v)); return f;
}

// bf16 hi/lo split + swizzled smem store
__device__ __forceinline__ uint32_t pkbf(__nv_bfloat16 a, __nv_bfloat16 b) {
    return (uint32_t)__bfloat16_as_ushort(a) | ((uint32_t)__bfloat16_as_ushort(b) << 16);
}
__device__ __forceinline__ void split_store(char* hi, char* lo, uint32_t sw, float4 v) {
    __nv_bfloat16 a0 = __float2bfloat16(v.x), a1 = __float2bfloat16(v.y),
                  a2 = __float2bfloat16(v.z), a3 = __float2bfloat16(v.w);
    float r0 = v.x - __bfloat162float(a0), r1 = v.y - __bfloat162float(a1),
          r2 = v.z - __bfloat162float(a2), r3 = v.w - __bfloat162float(a3);
    __nv_bfloat16 b0 = __float2bfloat16(r0), b1 = __float2bfloat16(r1),
                  b2 = __float2bfloat16(r2), b3 = __float2bfloat16(r3);
    *(uint2*)(hi + sw) = make_uint2(pkbf(a0, a1), pkbf(a2, a3));
    *(uint2*)(lo + sw) = make_uint2(pkbf(b0, b1), pkbf(b2, b3));
}

// ---------------------------------------------------------------------------
// One prep kernel: z=0..2 are 1024x1024 transposes; z=3 computes g_last.
// grid (32, 32, 4), block (32, 8)
__global__ __launch_bounds__(256)
void k_prep(const float* __restrict__ attn_w, const float* __restrict__ proj_w,
            const int* __restrict__ mask) {
    const int z = blockIdx.z;
    const int tx = threadIdx.x, ty = threadIdx.y;
    if (z == 3) {
        if (blockIdx.y == 0 && blockIdx.x < 4) {
            int i = blockIdx.x * 256 + ty * 32 + tx;
            int s = 0;
            #pragma unroll
            for (int j = 0; j < CSEQ; j++) s += mask[i * CSEQ + j];
            g_last[i] = s - 1;
        }
        return;
    }
    const float* in; int ldin; float* out;
    if (z == 0)      { in = attn_w;            ldin = 3 * CDIM; out = g_BT; }
    else if (z == 1) { in = proj_w;            ldin = CDIM;     out = g_BT + (size_t)CDIM * CDIM; }
    else             { in = attn_w + 2 * CDIM; ldin = 3 * CDIM; out = g_BT + 2 * (size_t)CDIM * CDIM; }

    __shared__ float t[32][33];
    const int k0 = blockIdx.y * 32, n0 = blockIdx.x * 32;
    #pragma unroll
    for (int i = ty; i < 32; i += 8)
        t[i][tx] = in[(size_t)(k0 + i) * ldin + n0 + tx];
    __syncthreads();
    #pragma unroll
    for (int i = ty; i < 32; i += 8)
        out[(size_t)(n0 + i) * CDIM + k0 + tx] = t[tx][i];
}

// ---------------------------------------------------------------------------
// bf16x3 warp-MMA GEMM with register-prefetch pipeline.
// C[MTILE x NTILE] per CTA = A(M,K) @ B^T(N,K), fp32 io.
// MODE 0 plain, 1 gather-A (g_last), 2 pos-add to A. blockIdx.z: head offsets.
template <int MTILE, int NTILE, int MODE>
__global__ __launch_bounds__(256)
void gemm_ws(const float* __restrict__ A, int lda, int a_zoff,
             const float* __restrict__ B, int ldb, int b_zoff,
             float* __restrict__ Cc, int ldc, int c_zoff,
             int K, const float* __restrict__ pos) {
    extern __shared__ char dsm[];
    const uint32_t raw = smem_to_u32(dsm);
    const uint32_t padb = (1024u - (raw & 1023u)) & 1023u;
    char* base = dsm + padb;
    const uint32_t sb = raw + padb;
    char* a_hi = base;
    char* a_lo = base + MTILE * 128;
    char* b_hi = base + 2 * MTILE * 128;
    char* b_lo = b_hi + NTILE * 128;
    const uint32_t A_HI = sb, A_LO = sb + MTILE * 128;
    const uint32_t B_HI = sb + 2 * MTILE * 128, B_LO = B_HI + NTILE * 128;

    const int tid = threadIdx.x, wid = tid >> 5, lane = tid & 31;
    const int hz = blockIdx.z;
    const int row0 = blockIdx.y * MTILE, col0 = blockIdx.x * NTILE;
    const float* Ab = A + (size_t)hz * a_zoff;
    const float* Bb = B + (size_t)hz * b_zoff;
    float* Cb = Cc + (size_t)hz * c_zoff;

    constexpr int WM = MTILE / 2, WN = NTILE / 4;
    constexpr int MT = WM / 16, NT = WN / 8;
    constexpr int AIT = MTILE / 16, BIT = NTILE / 16;
    const int m_w = (wid >> 2) * WM;
    const int n_w = (wid & 3) * WN;

    float cfr[MT][NT][4];
    #pragma unroll
    for (int i = 0; i < MT; i++)
        #pragma unroll
        for (int j = 0; j < NT; j++)
            #pragma unroll
            for (int q = 0; q < 4; q++) cfr[i][j][q] = 0.f;

    const float* aptr[AIT]; const float* pptr[AIT]; const float* bptr[BIT];
    uint32_t aswz[AIT], bswz[BIT];
    #pragma unroll
    for (int i = 0; i < AIT; i++) {
        int s = tid + i * 256;
        int r = s >> 4, kq = (s & 15) * 4;
        int grow = row0 + r;
        if (MODE == 1)
            aptr[i] = Ab + ((size_t)grow * CSEQ + g_last[grow]) * (size_t)lda + kq;
        else
            aptr[i] = Ab + (size_t)grow * (size_t)lda + kq;
        pptr[i] = (MODE == 2) ? (pos + (size_t)(grow & (WW - 1)) * CDIM + kq) : nullptr;
        aswz[i] = SMEM_SWIZZLE_128B((uint32_t)(r * 128 + kq * 2));
    }
    #pragma unroll
    for (int i = 0; i < BIT; i++) {
        int s = tid + i * 256;
        int r = s >> 4, kq = (s & 15) * 4;
        bptr[i] = Bb + (size_t)(col0 + r) * (size_t)ldb + kq;
        bswz[i] = SMEM_SWIZZLE_128B((uint32_t)(r * 128 + kq * 2));
    }

    const int a_row = lane & 15;
    const int a_kb  = (lane >> 4) * 16;
    const int b_row = (lane & 7) + ((lane >> 4) * 8);
    const int b_kb  = ((lane >> 3) & 1) * 16;

    float4 ra[AIT], rb[BIT];
    #pragma unroll
    for (int i = 0; i < AIT; i++) {
        ra[i] = *(const float4*)(aptr[i]);
        if (MODE == 2) {
            const float* pr = pptr[i];
            ra[i].x += pr[0]; ra[i].y += pr[1]; ra[i].z += pr[2]; ra[i].w += pr[3];
        }
    }
    #pragma unroll
    for (int i = 0; i < BIT; i++) rb[i] = *(const float4*)(bptr[i]);

    const int nch = K >> 6;
    for (int ch = 0; ch < nch; ch++) {
        #pragma unroll
        for (int i = 0; i < AIT; i++) split_store(a_hi, a_lo, aswz[i], ra[i]);
        #pragma unroll
        for (int i = 0; i < BIT; i++) split_store(b_hi, b_lo, bswz[i], rb[i]);
        __syncthreads();

        if (ch + 1 < nch) {
            const int kb = (ch + 1) << 6;
            #pragma unroll
            for (int i = 0; i < AIT; i++) {
                ra[i] = *(const float4*)(aptr[i] + kb);
                if (MODE == 2) {
                    const float* pr = pptr[i] + kb;
                    ra[i].x += pr[0]; ra[i].y += pr[1]; ra[i].z += pr[2]; ra[i].w += pr[3];
                }
            }
            #pragma unroll
            for (int i = 0; i < BIT; i++) rb[i] = *(const float4*)(bptr[i] + kb);
        }

        #pragma unroll
        for (int ks = 0; ks < 4; ks++) {
            const int ksb = ks * 32;
            uint32_t bh[NT][2], bl[NT][2];
            #pragma unroll
            for (int p = 0; p < NT / 2; p++) {
                uint32_t byte = (uint32_t)((n_w + p * 16 + b_row) * 128 + ksb + b_kb);
                uint32_t sw = SMEM_SWIZZLE_128B(byte);
                uint32_t r4[4];
                ldsm4(r4, B_HI + sw);
                bh[2*p][0] = r4[0]; bh[2*p][1] = r4[1];
                bh[2*p+1][0] = r4[2]; bh[2*p+1][1] = r4[3];
                ldsm4(r4, B_LO + sw);
                bl[2*p][0] = r4[0]; bl[2*p][1] = r4[1];
                bl[2*p+1][0] = r4[2]; bl[2*p+1][1] = r4[3];
            }
            uint32_t ah[MT][4], al[MT][4];
            #pragma unroll
            for (int mt = 0; mt < MT; mt++) {
                uint32_t byte = (uint32_t)((m_w + mt * 16 + a_row) * 128 + ksb + a_kb);
                uint32_t sw = SMEM_SWIZZLE_128B(byte);
                ldsm4(ah[mt], A_HI + sw);
                ldsm4(al[mt], A_LO + sw);
            }
            #pragma unroll
            for (int mt = 0; mt < MT; mt++)
                #pragma unroll
                for (int nt = 0; nt < NT; nt++) {
                    mma_bf16(cfr[mt][nt], ah[mt], bh[nt]);
                    mma_bf16(cfr[mt][nt], ah[mt], bl[nt]);
                    mma_bf16(cfr[mt][nt], al[mt], bh[nt]);
                }
        }
        __syncthreads();
    }

    #pragma unroll
    for (int mt = 0; mt < MT; mt++) {
        int r0 = row0 + m_w + mt * 16 + (lane >> 2);
        #pragma unroll
        for (int nt = 0; nt < NT; nt++) {
            int c0 = col0 + n_w + nt * 8 + (lane & 3) * 2;
            *(float2*)(Cb + (size_t)r0 * ldc + c0) = make_float2(cfr[mt][nt][0], cfr[mt][nt][1]);
            *(float2*)(Cb + (size_t)(r0 + 8) * ldc + c0) = make_float2(cfr[mt][nt][2], cfr[mt][nt][3]);
        }
    }
}

// ---------------------------------------------------------------------------
// Fused per-(b,w), cp.async pipelined over 4 c-chunks of 256.
// smem: xs full 32 x 1028 (resident), ts double-buffered 2 x 16 x 260, S/P.
#define XSTR 1028
#define TSTR 260
#define NCHUNK 4
#define CHUNK 256
#define OFF_TS (CSEQ * XSTR)                         // 32896
#define OFF_S  (OFF_TS + 2 * NH * TSTR)              // 41216
#define OFF_P  (OFF_S + CSEQ * 17)                   // 41760
#define SMEM_FLOATS (OFF_P + CSEQ * 17)              // 42304
#define SMEM_BYTES (SMEM_FLOATS * 4)                 // 169216

__global__ __launch_bounds__(1024)
void k_attn_fused3(const float* __restrict__ x) {
    extern __shared__ float sm[];
    float* xs  = sm;
    float* Ssm = sm + OFF_S;
    float* Psm = sm + OFF_P;
    const uint32_t sbase = smem_to_u32(sm);
    const uint32_t XS_U = sbase;
    const uint32_t TS_U = sbase + OFF_TS * 4;

    const int bw   = blockIdx.x;
    const int tid  = threadIdx.x;
    const int last = g_last[bw];
    const float* xbase = x   + (size_t)bw * CSEQ * CDIM;
    const float* tbase = g_t + (size_t)bw * (NH * CDIM);

    // per-thread load slots
    const int xr = tid >> 5, xg = tid & 31;      // x: 32 rows; 2 f4 per thread/chunk
    const int tr = tid >> 6, tg = tid & 63;      // t: 16 rows x 64 f4 = 1024 slots

    // issue chunk 0
    {
        cpa16(XS_U + (uint32_t)(xr * XSTR + xg * 4) * 4,
              xbase + (size_t)xr * CDIM + xg * 4);
        cpa16(XS_U + (uint32_t)(xr * XSTR + xg * 4 + 128) * 4,
              xbase + (size_t)xr * CDIM + xg * 4 + 128);
        cpa16(TS_U + (uint32_t)(tr * TSTR + tg * 4) * 4,
              tbase + (size_t)tr * CDIM + tg * 4);
        CP_COMMIT();
    }

    const int ks = tid & 15;
    const int j0 = ((tid >> 4) & 7) * 4;
    const int h0 = (tid >> 7) * 2;
    ull acc2[4][2] = {};

    #pragma unroll
    for (int ch = 0; ch < NCHUNK; ch++) {
        if (ch + 1 < NCHUNK) {
            const int cb = (ch + 1) * CHUNK;
            const int tbuf = (ch + 1) & 1;
            cpa16(XS_U + (uint32_t)(xr * XSTR + cb + xg * 4) * 4,
                  xbase + (size_t)xr * CDIM + cb + xg * 4);
            cpa16(XS_U + (uint32_t)(xr * XSTR + cb + xg * 4 + 128) * 4,
                  xbase + (size_t)xr * CDIM + cb + xg * 4 + 128);
            cpa16(TS_U + (uint32_t)((tbuf * NH + tr) * TSTR + tg * 4) * 4,
                  tbase + (size_t)tr * CDIM + cb + tg * 4);
            CP_COMMIT();
            CP_WAIT(1);
        } else {
            CP_WAIT(0);
        }
        __syncthreads();

        const float* tsb = sm + OFF_TS + (ch & 1) * NH * TSTR;
        #pragma unroll
        for (int k = 0; k < 4; k++) {
            const int g = k * 16 + ks;                 // 0..63 within chunk
            const int cx = ch * CHUNK + g * 4;
            const int ct = g * 4;
            float4 xv[4], tv[2];
            #pragma unroll
            for (int a = 0; a < 4; a++) xv[a] = *(const float4*)&xs[(j0 + a) * XSTR + cx];
            #pragma unroll
            for (int b = 0; b < 2; b++) tv[b] = *(const float4*)&tsb[(h0 + b) * TSTR + ct];
            #pragma unroll
            for (int a = 0; a < 4; a++) {
                ull xl = pack2f(xv[a].x, xv[a].y), xh = pack2f(xv[a].z, xv[a].w);
                #pragma unroll
                for (int b = 0; b < 2; b++) {
                    ffma2(acc2[a][b], xl, pack2f(tv[b].x, tv[b].y));
                    ffma2(acc2[a][b], xh, pack2f(tv[b].z, tv[b].w));
                }
            }
        }
        __syncthreads();
    }

    // reduce 16-way k-split within half-warps
    {
        float out = 0.f;
        #pragma unroll
        for (int a = 0; a < 4; a++)
            #pragma unroll
            for (int b = 0; b < 2; b++) {
                float2 u = unpack2(acc2[a][b]);
                float s = u.x + u.y;
                s += __shfl_xor_sync(0xffffffffu, s, 1);
                s += __shfl_xor_sync(0xffffffffu, s, 2);
                s += __shfl_xor_sync(0xffffffffu, s, 4);
                s += __shfl_xor_sync(0xffffffffu, s, 8);
                if (ks == a * 2 + b) out = s;
            }
        if (ks < 8)
            Ssm[(j0 + (ks >> 1)) * 17 + h0 + (ks & 1)] = out * 0.125f;
    }
    __syncthreads();

    // softmax (warp per head; warps 0-15)
    if (tid < 512) {
        const int h = tid >> 5, lane = tid & 31;
        float s = (lane <= last) ? Ssm[lane * 17 + h] : -INFINITY;
        float m = s;
        #pragma unroll
        for (int off = 16; off; off >>= 1) m = fmaxf(m, __shfl_xor_sync(0xffffffffu, m, off));
        float e = (lane <= last) ? __expf(s - m) : 0.f;
        float sum = e;
        #pragma unroll
        for (int off = 16; off; off >>= 1) sum += __shfl_xor_sync(0xffffffffu, sum, off);
        Psm[lane * 17 + h] = e / sum;
    }
    __syncthreads();

    // phase 3: mix A[h][c] = sum_j P[j][h] x[j][c]  (2h x 8c per thread)
    {
        const int hp = tid >> 7;
        const int cg = tid & 127;

        ull acc[2][4] = {};
        #pragma unroll 8
        for (int j = 0; j < CSEQ; j++) {
            ull p0 = pack2(Psm[j * 17 + hp * 2]);
            ull p1 = pack2(Psm[j * 17 + hp * 2 + 1]);
            float4 x0 = *(const float4*)&xs[j * XSTR + cg * 8];
            float4 x1 = *(const float4*)&xs[j * XSTR + cg * 8 + 4];
            ull xp[4] = {pack2f(x0.x, x0.y), pack2f(x0.z, x0.w),
                         pack2f(x1.x, x1.y), pack2f(x1.z, x1.w)};
            #pragma unroll
            for (int q = 0; q < 4; q++) {
                ffma2(acc[0][q], p0, xp[q]);
                ffma2(acc[1][q], p1, xp[q]);
            }
        }
        float* Abase = g_A + (size_t)bw * (NH * CDIM);
        #pragma unroll
        for (int b = 0; b < 2; b++) {
            float* dst = Abase + (size_t)(hp * 2 + b) * CDIM + cg * 8;
            float2 u0 = unpack2(acc[b][0]), u1 = unpack2(acc[b][1]);
            float2 u2 = unpack2(acc[b][2]), u3 = unpack2(acc[b][3]);
            ((float4*)dst)[0] = make_float4(u0.x, u0.y, u1.x, u1.y);
            ((float4*)dst)[1] = make_float4(u2.x, u2.y, u3.x, u3.y);
        }
    }
}

// ---------------------------------------------------------------------------
extern "C" void kernel_launch(void* const* d_in, const int* in_sizes, int n_in,
                              void* d_out, int out_size) {
    const float* x      = (const float*)d_in[0];  // (4,256,32,1024)
    const int*   mask   = (const int*)  d_in[1];  // (4,256,32)
    const float* pos    = (const float*)d_in[2];  // (256,1024)
    const float* attn_w = (const float*)d_in[3];  // (1024,3072)
    const float* proj_w = (const float*)d_in[4];  // (1024,1024)
    float*       out    = (float*)d_out;          // (4,256,1024)

    float* qb;  cudaGetSymbolAddress((void**)&qb,  g_q);
    float* tb;  cudaGetSymbolAddress((void**)&tb,  g_t);
    float* ab;  cudaGetSymbolAddress((void**)&ab,  g_A);
    float* ob;  cudaGetSymbolAddress((void**)&ob,  g_o);
    float* btb; cudaGetSymbolAddress((void**)&btb, g_BT);
    float* BTq = btb;
    float* BTp = btb + (size_t)CDIM * CDIM;
    float* BTv = btb + 2 * (size_t)CDIM * CDIM;

    const int SM_6428  = 2 * 64 * 128 + 2 * 128 * 128 + 1024;   // 50176
    const int SM_12828 = 2 * 128 * 128 + 2 * 128 * 128 + 1024;  // 66560
    const int SM_12864 = 2 * 128 * 128 + 2 * 64 * 128 + 1024;   // 50176

    static int attr_set = 0;
    if (!attr_set) {
        cudaFuncSetAttribute(k_attn_fused3, cudaFuncAttributeMaxDynamicSharedMemorySize, SMEM_BYTES);
        cudaFuncSetAttribute(gemm_ws<64, 128, 1>,  cudaFuncAttributeMaxDynamicSharedMemorySize, SM_6428);
        cudaFuncSetAttribute(gemm_ws<64, 128, 2>,  cudaFuncAttributeMaxDynamicSharedMemorySize, SM_6428);
        cudaFuncSetAttribute(gemm_ws<128, 128, 0>, cudaFuncAttributeMaxDynamicSharedMemorySize, SM_12828);
        cudaFuncSetAttribute(gemm_ws<128, 64, 0>,  cudaFuncAttributeMaxDynamicSharedMemorySize, SM_12864);
        attr_set = 1;
    }

    // 1) prep: 3 transposes + g_last in one launch
    {
        dim3 grid(32, 32, 4), blk(32, 8);
        k_prep<<<grid, blk>>>(attn_w, proj_w, mask);
    }

    // 2) Q = gather(x) @ Wq   [1024 x 1024 x 1024]
    {
        dim3 grid(8, 16, 1);
        gemm_ws<64, 128, 1><<<grid, 256, SM_6428>>>(x, CDIM, 0, BTq, CDIM, 0,
                                                    qb, CDIM, 0, CDIM, nullptr);
    }

    // 3) t[bw][h] = q_h @ Wk_h^T   [per head: 1024 x 1024 x 64]
    {
        dim3 grid(8, 8, NH);
        gemm_ws<128, 128, 0><<<grid, 256, SM_12828>>>(qb, CDIM, HD,
                                                      attn_w + CDIM, 3 * CDIM, HD,
                                                      tb, NH * CDIM, CDIM, HD, nullptr);
    }

    // 4) fused scores + softmax + mix (cp.async pipelined, 4 chunks)
    k_attn_fused3<<<BW, 1024, SMEM_BYTES>>>(x);

    // 5) O_h = A_h @ Wv_h   [per head: 1024 x 64 x 1024]
    {
        dim3 grid(1, 8, NH);
        gemm_ws<128, 64, 0><<<grid, 256, SM_12864>>>(ab, NH * CDIM, CDIM,
                                                     BTv, CDIM, HD * CDIM,
                                                     ob, CDIM, HD, CDIM, nullptr);
    }

    // 6) out = (O + pos) @ proj_w   [1024 x 1024 x 1024]
    {
        dim3 grid(8, 16, 1);
        gemm_ws<64, 128, 2><<<grid, 256, SM_6428>>>(ob, CDIM, 0, BTp, CDIM, 0,
                                                    out, CDIM, 0, CDIM, pos);
    }
}

// round 8
// speedup vs baseline: 14.1001x; 1.2403x over previous
#include <cuda_runtime.h>
#include <cuda_bf16.h>
#include <cstdint>
#include <math.h>

#define BB   4
#define WW   256
#define CSEQ 32
#define CDIM 1024
#define NH   16
#define HD   64
#define BW   1024

typedef unsigned long long ull;

// Scratch (device globals: allocation-free rule)
__device__ float g_q [(size_t)BW * CDIM];
__device__ float g_t [(size_t)BW * NH * CDIM];
__device__ float g_A [(size_t)BW * NH * CDIM];
__device__ float g_o [(size_t)BW * CDIM];
__device__ float g_BT[3 * (size_t)CDIM * CDIM];   // transposed Wq, proj_w, Wv
__device__ int   g_last[BW];

// ===========================================================================
__device__ __forceinline__ uint32_t smem_to_u32(const void* smem_ptr) {
    uint32_t addr;
    asm("{ .reg .u64 tmp; cvta.to.shared.u64 tmp, %1; cvt.u32.u64 %0, tmp; }"
        : "=r"(addr) : "l"(smem_ptr));
    return addr;
}
#define SMEM_SWIZZLE_128B(byte_offset) ((byte_offset) ^ (((byte_offset) >> 3) & 0x70))

__device__ __forceinline__ void mma_bf16(float* d, const uint32_t* a, const uint32_t* b) {
    asm volatile(
        "mma.sync.aligned.m16n8k16.row.col.f32.bf16.bf16.f32 "
        "{%0,%1,%2,%3}, {%4,%5,%6,%7}, {%8,%9}, {%0,%1,%2,%3};"
        : "+f"(d[0]), "+f"(d[1]), "+f"(d[2]), "+f"(d[3])
        : "r"(a[0]), "r"(a[1]), "r"(a[2]), "r"(a[3]), "r"(b[0]), "r"(b[1]));
}
__device__ __forceinline__ void ldsm4(uint32_t* r, uint32_t addr) {
    asm volatile("ldmatrix.sync.aligned.m8n8.x4.shared.b16 {%0,%1,%2,%3}, [%4];"
        : "=r"(r[0]), "=r"(r[1]), "=r"(r[2]), "=r"(r[3]) : "r"(addr));
}
__device__ __forceinline__ void ldsm4t(uint32_t* r, uint32_t addr) {
    asm volatile("ldmatrix.sync.aligned.m8n8.x4.trans.shared.b16 {%0,%1,%2,%3}, [%4];"
        : "=r"(r[0]), "=r"(r[1]), "=r"(r[2]), "=r"(r[3]) : "r"(addr));
}

// bf16 hi/lo split + swizzled smem store
__device__ __forceinline__ uint32_t pkbf(__nv_bfloat16 a, __nv_bfloat16 b) {
    return (uint32_t)__bfloat16_as_ushort(a) | ((uint32_t)__bfloat16_as_ushort(b) << 16);
}
__device__ __forceinline__ void split_store(char* hi, char* lo, uint32_t sw, float4 v) {
    __nv_bfloat16 a0 = __float2bfloat16(v.x), a1 = __float2bfloat16(v.y),
                  a2 = __float2bfloat16(v.z), a3 = __float2bfloat16(v.w);
    float r0 = v.x - __bfloat162float(a0), r1 = v.y - __bfloat162float(a1),
          r2 = v.z - __bfloat162float(a2), r3 = v.w - __bfloat162float(a3);
    __nv_bfloat16 b0 = __float2bfloat16(r0), b1 = __float2bfloat16(r1),
                  b2 = __float2bfloat16(r2), b3 = __float2bfloat16(r3);
    *(uint2*)(hi + sw) = make_uint2(pkbf(a0, a1), pkbf(a2, a3));
    *(uint2*)(lo + sw) = make_uint2(pkbf(b0, b1), pkbf(b2, b3));
}

// ---------------------------------------------------------------------------
// One prep kernel: z=0..2 are 1024x1024 transposes; z=3 computes g_last.
__global__ __launch_bounds__(256)
void k_prep(const float* __restrict__ attn_w, const float* __restrict__ proj_w,
            const int* __restrict__ mask) {
    const int z = blockIdx.z;
    const int tx = threadIdx.x, ty = threadIdx.y;
    if (z == 3) {
        if (blockIdx.y == 0 && blockIdx.x < 4) {
            int i = blockIdx.x * 256 + ty * 32 + tx;
            int s = 0;
            #pragma unroll
            for (int j = 0; j < CSEQ; j++) s += mask[i * CSEQ + j];
            g_last[i] = s - 1;
        }
        return;
    }
    const float* in; int ldin; float* out;
    if (z == 0)      { in = attn_w;            ldin = 3 * CDIM; out = g_BT; }
    else if (z == 1) { in = proj_w;            ldin = CDIM;     out = g_BT + (size_t)CDIM * CDIM; }
    else             { in = attn_w + 2 * CDIM; ldin = 3 * CDIM; out = g_BT + 2 * (size_t)CDIM * CDIM; }

    __shared__ float t[32][33];
    const int k0 = blockIdx.y * 32, n0 = blockIdx.x * 32;
    #pragma unroll
    for (int i = ty; i < 32; i += 8)
        t[i][tx] = in[(size_t)(k0 + i) * ldin + n0 + tx];
    __syncthreads();
    #pragma unroll
    for (int i = ty; i < 32; i += 8)
        out[(size_t)(n0 + i) * CDIM + k0 + tx] = t[tx][i];
}

// ---------------------------------------------------------------------------
// bf16x3 warp-MMA GEMM with register-prefetch pipeline. (unchanged, validated)
template <int MTILE, int NTILE, int MODE>
__global__ __launch_bounds__(256)
void gemm_ws(const float* __restrict__ A, int lda, int a_zoff,
             const float* __restrict__ B, int ldb, int b_zoff,
             float* __restrict__ Cc, int ldc, int c_zoff,
             int K, const float* __restrict__ pos) {
    extern __shared__ char dsm[];
    const uint32_t raw = smem_to_u32(dsm);
    const uint32_t padb = (1024u - (raw & 1023u)) & 1023u;
    char* base = dsm + padb;
    const uint32_t sb = raw + padb;
    char* a_hi = base;
    char* a_lo = base + MTILE * 128;
    char* b_hi = base + 2 * MTILE * 128;
    char* b_lo = b_hi + NTILE * 128;
    const uint32_t A_HI = sb, A_LO = sb + MTILE * 128;
    const uint32_t B_HI = sb + 2 * MTILE * 128, B_LO = B_HI + NTILE * 128;

    const int tid = threadIdx.x, wid = tid >> 5, lane = tid & 31;
    const int hz = blockIdx.z;
    const int row0 = blockIdx.y * MTILE, col0 = blockIdx.x * NTILE;
    const float* Ab = A + (size_t)hz * a_zoff;
    const float* Bb = B + (size_t)hz * b_zoff;
    float* Cb = Cc + (size_t)hz * c_zoff;

    constexpr int WM = MTILE / 2, WN = NTILE / 4;
    constexpr int MT = WM / 16, NT = WN / 8;
    constexpr int AIT = MTILE / 16, BIT = NTILE / 16;
    const int m_w = (wid >> 2) * WM;
    const int n_w = (wid & 3) * WN;

    float cfr[MT][NT][4];
    #pragma unroll
    for (int i = 0; i < MT; i++)
        #pragma unroll
        for (int j = 0; j < NT; j++)
            #pragma unroll
            for (int q = 0; q < 4; q++) cfr[i][j][q] = 0.f;

    const float* aptr[AIT]; const float* pptr[AIT]; const float* bptr[BIT];
    uint32_t aswz[AIT], bswz[BIT];
    #pragma unroll
    for (int i = 0; i < AIT; i++) {
        int s = tid + i * 256;
        int r = s >> 4, kq = (s & 15) * 4;
        int grow = row0 + r;
        if (MODE == 1)
            aptr[i] = Ab + ((size_t)grow * CSEQ + g_last[grow]) * (size_t)lda + kq;
        else
            aptr[i] = Ab + (size_t)grow * (size_t)lda + kq;
        pptr[i] = (MODE == 2) ? (pos + (size_t)(grow & (WW - 1)) * CDIM + kq) : nullptr;
        aswz[i] = SMEM_SWIZZLE_128B((uint32_t)(r * 128 + kq * 2));
    }
    #pragma unroll
    for (int i = 0; i < BIT; i++) {
        int s = tid + i * 256;
        int r = s >> 4, kq = (s & 15) * 4;
        bptr[i] = Bb + (size_t)(col0 + r) * (size_t)ldb + kq;
        bswz[i] = SMEM_SWIZZLE_128B((uint32_t)(r * 128 + kq * 2));
    }

    const int a_row = lane & 15;
    const int a_kb  = (lane >> 4) * 16;
    const int b_row = (lane & 7) + ((lane >> 4) * 8);
    const int b_kb  = ((lane >> 3) & 1) * 16;

    float4 ra[AIT], rb[BIT];
    #pragma unroll
    for (int i = 0; i < AIT; i++) {
        ra[i] = *(const float4*)(aptr[i]);
        if (MODE == 2) {
            const float* pr = pptr[i];
            ra[i].x += pr[0]; ra[i].y += pr[1]; ra[i].z += pr[2]; ra[i].w += pr[3];
        }
    }
    #pragma unroll
    for (int i = 0; i < BIT; i++) rb[i] = *(const float4*)(bptr[i]);

    const int nch = K >> 6;
    for (int ch = 0; ch < nch; ch++) {
        #pragma unroll
        for (int i = 0; i < AIT; i++) split_store(a_hi, a_lo, aswz[i], ra[i]);
        #pragma unroll
        for (int i = 0; i < BIT; i++) split_store(b_hi, b_lo, bswz[i], rb[i]);
        __syncthreads();

        if (ch + 1 < nch) {
            const int kb = (ch + 1) << 6;
            #pragma unroll
            for (int i = 0; i < AIT; i++) {
                ra[i] = *(const float4*)(aptr[i] + kb);
                if (MODE == 2) {
                    const float* pr = pptr[i] + kb;
                    ra[i].x += pr[0]; ra[i].y += pr[1]; ra[i].z += pr[2]; ra[i].w += pr[3];
                }
            }
            #pragma unroll
            for (int i = 0; i < BIT; i++) rb[i] = *(const float4*)(bptr[i] + kb);
        }

        #pragma unroll
        for (int ks = 0; ks < 4; ks++) {
            const int ksb = ks * 32;
            uint32_t bh[NT][2], bl[NT][2];
            #pragma unroll
            for (int p = 0; p < NT / 2; p++) {
                uint32_t byte = (uint32_t)((n_w + p * 16 + b_row) * 128 + ksb + b_kb);
                uint32_t sw = SMEM_SWIZZLE_128B(byte);
                uint32_t r4[4];
                ldsm4(r4, B_HI + sw);
                bh[2*p][0] = r4[0]; bh[2*p][1] = r4[1];
                bh[2*p+1][0] = r4[2]; bh[2*p+1][1] = r4[3];
                ldsm4(r4, B_LO + sw);
                bl[2*p][0] = r4[0]; bl[2*p][1] = r4[1];
                bl[2*p+1][0] = r4[2]; bl[2*p+1][1] = r4[3];
            }
            uint32_t ah[MT][4], al[MT][4];
            #pragma unroll
            for (int mt = 0; mt < MT; mt++) {
                uint32_t byte = (uint32_t)((m_w + mt * 16 + a_row) * 128 + ksb + a_kb);
                uint32_t sw = SMEM_SWIZZLE_128B(byte);
                ldsm4(ah[mt], A_HI + sw);
                ldsm4(al[mt], A_LO + sw);
            }
            #pragma unroll
            for (int mt = 0; mt < MT; mt++)
                #pragma unroll
                for (int nt = 0; nt < NT; nt++) {
                    mma_bf16(cfr[mt][nt], ah[mt], bh[nt]);
                    mma_bf16(cfr[mt][nt], ah[mt], bl[nt]);
                    mma_bf16(cfr[mt][nt], al[mt], bh[nt]);
                }
        }
        __syncthreads();
    }

    #pragma unroll
    for (int mt = 0; mt < MT; mt++) {
        int r0 = row0 + m_w + mt * 16 + (lane >> 2);
        #pragma unroll
        for (int nt = 0; nt < NT; nt++) {
            int c0 = col0 + n_w + nt * 8 + (lane & 3) * 2;
            *(float2*)(Cb + (size_t)r0 * ldc + c0) = make_float2(cfr[mt][nt][0], cfr[mt][nt][1]);
            *(float2*)(Cb + (size_t)(r0 + 8) * ldc + c0) = make_float2(cfr[mt][nt][2], cfr[mt][nt][3]);
        }
    }
}

// ---------------------------------------------------------------------------
// Fused per-(b,w), tensor-core edition.
// smem layout (bytes from 1024-aligned base):
//   XHI 0       : x hi plane, 16 chunks x (32 rows x 128B)  = 65536
//   XLO 65536   : x lo plane                                 = 65536
//   THI 131072  : t hi plane, 16 chunks x (16 rows x 128B)   = 32768
//   TLO 163840  : t lo plane                                 = 32768
//   SS  196608  : S fp32 [32][17]                            = 2176
//   PTH 199680  : P^T hi bf16, 16 rows x 128B                = 2048
//   PTL 201728  : P^T lo bf16                                = 2048
#define F4_XHI 0
#define F4_XLO 65536
#define F4_THI 131072
#define F4_TLO 163840
#define F4_SS  196608
#define F4_PTH 199680
#define F4_PTL 201728
#define F4_SMEM (203776 + 1024)

__global__ __launch_bounds__(1024)
void k_attn_fused4(const float* __restrict__ x) {
    extern __shared__ char fsm[];
    const uint32_t raw = smem_to_u32(fsm);
    const uint32_t padb = (1024u - (raw & 1023u)) & 1023u;
    char* base = fsm + padb;
    const uint32_t sb = raw + padb;

    char* xhi = base + F4_XHI;  char* xlo = base + F4_XLO;
    char* thi = base + F4_THI;  char* tlo = base + F4_TLO;
    float* Ssm = (float*)(base + F4_SS);
    char* pth = base + F4_PTH;  char* ptl = base + F4_PTL;
    const uint32_t XHI_U = sb + F4_XHI, XLO_U = sb + F4_XLO;
    const uint32_t THI_U = sb + F4_THI, TLO_U = sb + F4_TLO;
    const uint32_t PTH_U = sb + F4_PTH, PTL_U = sb + F4_PTL;

    const int bw   = blockIdx.x;
    const int tid  = threadIdx.x;
    const int wid  = tid >> 5, lane = tid & 31;
    const int last = g_last[bw];
    const float* xbase = x   + (size_t)bw * CSEQ * CDIM;
    const float* tbase = g_t + (size_t)bw * (NH * CDIM);

    // ---- load + split x (32x1024) and t (16x1024) into bf16 planes ----
    {
        const int xr = tid >> 5, xg = (tid & 31) * 4;
        #pragma unroll
        for (int i = 0; i < 8; i++) {
            int c = xg + i * 128;
            float4 v = *(const float4*)(xbase + (size_t)xr * CDIM + c);
            int chunk = c >> 6;
            uint32_t sw = SMEM_SWIZZLE_128B((uint32_t)(xr * 128 + (c & 63) * 2));
            split_store(xhi + chunk * 4096, xlo + chunk * 4096, sw, v);
        }
        const int trr = tid >> 6, tg = (tid & 63) * 4;
        #pragma unroll
        for (int i = 0; i < 4; i++) {
            int c = tg + i * 256;
            float4 v = *(const float4*)(tbase + (size_t)trr * CDIM + c);
            int chunk = c >> 6;
            uint32_t sw = SMEM_SWIZZLE_128B((uint32_t)(trr * 128 + (c & 63) * 2));
            split_store(thi + chunk * 2048, tlo + chunk * 2048, sw, v);
        }
        if (tid < 544) Ssm[tid] = 0.f;
    }
    __syncthreads();

    // ---- phase 1: S(32j x 16h) = X @ T^T via mma, k-split 8 x mn-split 4 ----
    {
        const int mt  = (wid >> 1) & 1;       // j-tile
        const int ntw = wid & 1;              // h-tile
        const int ks  = wid >> 2;             // k-slice 0..7 (128 k each)
        float c4[4] = {0.f, 0.f, 0.f, 0.f};

        const int arow = (mt * 16 + (lane & 15)) * 128 + (lane >> 4) * 16;
        const int brow = ((lane & 7) + ((lane >> 4) & 1) * 8) * 128 + ((lane >> 3) & 1) * 16;

        #pragma unroll
        for (int cc = 0; cc < 2; cc++) {
            const int chunk = ks * 2 + cc;
            const uint32_t xb  = XHI_U + chunk * 4096, xbl = XLO_U + chunk * 4096;
            const uint32_t tb  = THI_U + chunk * 2048, tbl = TLO_U + chunk * 2048;
            #pragma unroll
            for (int kk = 0; kk < 4; kk++) {
                const int ksb = kk * 32;
                uint32_t ah[4], al[4], r4[4], r4l[4];
                ldsm4(ah, xb  + SMEM_SWIZZLE_128B((uint32_t)(arow + ksb)));
                ldsm4(al, xbl + SMEM_SWIZZLE_128B((uint32_t)(arow + ksb)));
                ldsm4(r4,  tb  + SMEM_SWIZZLE_128B((uint32_t)(brow + ksb)));
                ldsm4(r4l, tbl + SMEM_SWIZZLE_128B((uint32_t)(brow + ksb)));
                uint32_t bh[2] = {r4[2 * ntw],  r4[2 * ntw + 1]};
                uint32_t bl[2] = {r4l[2 * ntw], r4l[2 * ntw + 1]};
                mma_bf16(c4, ah, bh);
                mma_bf16(c4, ah, bl);
                mma_bf16(c4, al, bh);
            }
        }
        const int r0 = mt * 16 + (lane >> 2);
        const int c0 = ntw * 8 + (lane & 3) * 2;
        atomicAdd(&Ssm[r0 * 17 + c0],           c4[0]);
        atomicAdd(&Ssm[r0 * 17 + c0 + 1],       c4[1]);
        atomicAdd(&Ssm[(r0 + 8) * 17 + c0],     c4[2]);
        atomicAdd(&Ssm[(r0 + 8) * 17 + c0 + 1], c4[3]);
    }
    __syncthreads();

    // ---- phase 2: softmax (warp per head) + write P^T bf16 hi/lo planes ----
    if (tid < 512) {
        const int h = tid >> 5, j = lane;
        float s = (j <= last) ? Ssm[j * 17 + h] * 0.125f : -INFINITY;
        float m = s;
        #pragma unroll
        for (int off = 16; off; off >>= 1) m = fmaxf(m, __shfl_xor_sync(0xffffffffu, m, off));
        float e = (j <= last) ? __expf(s - m) : 0.f;
        float sum = e;
        #pragma unroll
        for (int off = 16; off; off >>= 1) sum += __shfl_xor_sync(0xffffffffu, sum, off);
        float p = e / sum;
        __nv_bfloat16 ph = __float2bfloat16(p);
        __nv_bfloat16 pl = __float2bfloat16(p - __bfloat162float(ph));
        uint32_t sw = SMEM_SWIZZLE_128B((uint32_t)(h * 128 + j * 2));
        *(__nv_bfloat16*)(pth + sw) = ph;
        *(__nv_bfloat16*)(ptl + sw) = pl;
    }
    __syncthreads();

    // ---- phase 3: A(16h x 1024c) = P^T @ X via mma; warp w owns 32 c ----
    {
        const int cbase = wid * 32;
        uint32_t aPh[2][4], aPl[2][4];
        #pragma unroll
        for (int jt = 0; jt < 2; jt++) {
            uint32_t off = SMEM_SWIZZLE_128B((uint32_t)((lane & 15) * 128 + jt * 32 + (lane >> 4) * 16));
            ldsm4(aPh[jt], PTH_U + off);
            ldsm4(aPl[jt], PTL_U + off);
        }
        float c3[4][4];
        #pragma unroll
        for (int nt = 0; nt < 4; nt++)
            #pragma unroll
            for (int q = 0; q < 4; q++) c3[nt][q] = 0.f;

        #pragma unroll
        for (int ct = 0; ct < 2; ct++) {
            const int c0 = cbase + ct * 16;
            const int chunk = c0 >> 6, cin = c0 & 63;
            #pragma unroll
            for (int jt = 0; jt < 2; jt++) {
                const int jrow = (lane & 7) + ((lane >> 3) & 1) * 8 + jt * 16;
                uint32_t off = SMEM_SWIZZLE_128B(
                    (uint32_t)(jrow * 128 + (cin + ((lane >> 4) & 1) * 8) * 2));
                uint32_t bx[4], bxl[4];
                ldsm4t(bx,  XHI_U + chunk * 4096 + off);
                ldsm4t(bxl, XLO_U + chunk * 4096 + off);
                #pragma unroll
                for (int half = 0; half < 2; half++) {
                    const int nt = ct * 2 + half;
                    uint32_t bh[2] = {bx[2 * half],  bx[2 * half + 1]};
                    uint32_t bl[2] = {bxl[2 * half], bxl[2 * half + 1]};
                    mma_bf16(c3[nt], aPh[jt], bh);
                    mma_bf16(c3[nt], aPh[jt], bl);
                    mma_bf16(c3[nt], aPl[jt], bh);
                }
            }
        }
        float* Ab = g_A + (size_t)bw * (NH * CDIM);
        #pragma unroll
        for (int nt = 0; nt < 4; nt++) {
            const int col = cbase + nt * 8 + (lane & 3) * 2;
            *(float2*)(Ab + (size_t)(lane >> 2) * CDIM + col) =
                make_float2(c3[nt][0], c3[nt][1]);
            *(float2*)(Ab + (size_t)((lane >> 2) + 8) * CDIM + col) =
                make_float2(c3[nt][2], c3[nt][3]);
        }
    }
}

// ---------------------------------------------------------------------------
extern "C" void kernel_launch(void* const* d_in, const int* in_sizes, int n_in,
                              void* d_out, int out_size) {
    const float* x      = (const float*)d_in[0];  // (4,256,32,1024)
    const int*   mask   = (const int*)  d_in[1];  // (4,256,32)
    const float* pos    = (const float*)d_in[2];  // (256,1024)
    const float* attn_w = (const float*)d_in[3];  // (1024,3072)
    const float* proj_w = (const float*)d_in[4];  // (1024,1024)
    float*       out    = (float*)d_out;          // (4,256,1024)

    float* qb;  cudaGetSymbolAddress((void**)&qb,  g_q);
    float* tb;  cudaGetSymbolAddress((void**)&tb,  g_t);
    float* ab;  cudaGetSymbolAddress((void**)&ab,  g_A);
    float* ob;  cudaGetSymbolAddress((void**)&ob,  g_o);
    float* btb; cudaGetSymbolAddress((void**)&btb, g_BT);
    float* BTq = btb;
    float* BTp = btb + (size_t)CDIM * CDIM;
    float* BTv = btb + 2 * (size_t)CDIM * CDIM;

    const int SM_6428  = 2 * 64 * 128 + 2 * 128 * 128 + 1024;   // 50176
    const int SM_12828 = 2 * 128 * 128 + 2 * 128 * 128 + 1024;  // 66560
    const int SM_12864 = 2 * 128 * 128 + 2 * 64 * 128 + 1024;   // 50176

    static int attr_set = 0;
    if (!attr_set) {
        cudaFuncSetAttribute(k_attn_fused4, cudaFuncAttributeMaxDynamicSharedMemorySize, F4_SMEM);
        cudaFuncSetAttribute(gemm_ws<64, 128, 1>,  cudaFuncAttributeMaxDynamicSharedMemorySize, SM_6428);
        cudaFuncSetAttribute(gemm_ws<64, 128, 2>,  cudaFuncAttributeMaxDynamicSharedMemorySize, SM_6428);
        cudaFuncSetAttribute(gemm_ws<128, 128, 0>, cudaFuncAttributeMaxDynamicSharedMemorySize, SM_12828);
        cudaFuncSetAttribute(gemm_ws<128, 64, 0>,  cudaFuncAttributeMaxDynamicSharedMemorySize, SM_12864);
        attr_set = 1;
    }

    // 1) prep: 3 transposes + g_last in one launch
    {
        dim3 grid(32, 32, 4), blk(32, 8);
        k_prep<<<grid, blk>>>(attn_w, proj_w, mask);
    }

    // 2) Q = gather(x) @ Wq   [1024 x 1024 x 1024]
    {
        dim3 grid(8, 16, 1);
        gemm_ws<64, 128, 1><<<grid, 256, SM_6428>>>(x, CDIM, 0, BTq, CDIM, 0,
                                                    qb, CDIM, 0, CDIM, nullptr);
    }

    // 3) t[bw][h] = q_h @ Wk_h^T   [per head: 1024 x 1024 x 64]
    {
        dim3 grid(8, 8, NH);
        gemm_ws<128, 128, 0><<<grid, 256, SM_12828>>>(qb, CDIM, HD,
                                                      attn_w + CDIM, 3 * CDIM, HD,
                                                      tb, NH * CDIM, CDIM, HD, nullptr);
    }

    // 4) fused scores + softmax + mix (tensor-core)
    k_attn_fused4<<<BW, 1024, F4_SMEM>>>(x);

    // 5) O_h = A_h @ Wv_h   [per head: 1024 x 64 x 1024]
    {
        dim3 grid(1, 8, NH);
        gemm_ws<128, 64, 0><<<grid, 256, SM_12864>>>(ab, NH * CDIM, CDIM,
                                                     BTv, CDIM, HD * CDIM,
                                                     ob, CDIM, HD, CDIM, nullptr);
    }

    // 6) out = (O + pos) @ proj_w   [1024 x 1024 x 1024]
    {
        dim3 grid(8, 16, 1);
        gemm_ws<64, 128, 2><<<grid, 256, SM_6428>>>(ob, CDIM, 0, BTp, CDIM, 0,
                                                    out, CDIM, 0, CDIM, pos);
    }
}